// round 3
// baseline (speedup 1.0000x reference)
#include <cuda_runtime.h>
#include <math.h>

// Problem constants
#define BB    2
#define SS    1024
#define DD    1024
#define NH    16
#define HD    64
#define NL    12
#define DFF   4096
#define RH    128
#define VOC   32000
#define MM    (BB*SS)          // 2048 tokens
#define BHT   (BB*NH)          // 32 batch-heads

typedef unsigned long long ull;

// packed fp32x2 FMA (Blackwell FFMA2) — two IEEE fp32 FMAs per instruction
static __device__ __forceinline__ void fma2(ull &acc, ull a, ull b) {
    asm("fma.rn.f32x2 %0, %1, %2, %0;" : "+l"(acc) : "l"(a), "l"(b));
}
static __device__ __forceinline__ float lo32(ull v) { return __uint_as_float((unsigned)v); }
static __device__ __forceinline__ float hi32(ull v) { return __uint_as_float((unsigned)(v >> 32)); }

// ---------------- static device scratch (no allocations allowed) ----------------
__device__ float g_h [MM*DD];
__device__ float g_h1[MM*DD];
__device__ float g_t [MM*DD];
__device__ float g_q [MM*DD];
__device__ float g_k [MM*DD];
__device__ float g_v [MM*DD];
__device__ float g_a [MM*DD];
__device__ float g_ht[MM*DD];
__device__ float g_f1[MM*DFF];
__device__ float g_zr[MM*RH];
__device__ float g_sc[(size_t)BHT*SS*SS];   // 128 MB attention scores
__device__ unsigned char g_skip[MM];
__device__ int g_cnt[3];

// ---------------- init / counters ----------------
__global__ void zero_cnt_kernel() {
    if (threadIdx.x < 3) g_cnt[threadIdx.x] = 0;
}

// ---------------- embedding + positional encoding ----------------
__global__ __launch_bounds__(256) void embed_kernel(const int* __restrict__ x,
                                                    const float* __restrict__ emb) {
    int tok = blockIdx.x;
    int s = tok % SS;
    int id = x[tok];
    int d0 = threadIdx.x * 4;
    float4 ev = *(const float4*)(emb + (size_t)id * DD + d0);
    float o[4] = {ev.x, ev.y, ev.z, ev.w};
#pragma unroll
    for (int j = 0; j < 4; j++) {
        int d = d0 + j;
        float ang = (float)s * expf((float)(d & ~1) * (-9.210340371976184f / 1024.0f));
        float pe = (d & 1) ? cosf(ang) : sinf(ang);
        o[j] = o[j] * 32.0f + pe;   // sqrt(1024)=32
    }
    *(float4*)(g_h + (size_t)tok * DD + d0) = make_float4(o[0], o[1], o[2], o[3]);
}

// ---------------- tiled SGEMM (FFMA2): C = [res +] A(MxK)@B(KxN) [+bias] [relu] -----
// Tiles: 128(M) x 128(N) x 16(K). 256 threads, each computes 8x8.
// Accumulators packed along M (pairs); B duplicated in smem so (b,b) pairs load directly.
// Requires M%128==0, N%128==0, K%16==0.
__global__ __launch_bounds__(256, 2) void sgemm_kernel(const float* __restrict__ A,
                                                       const float* __restrict__ B,
                                                       const float* __restrict__ bias,
                                                       const float* __restrict__ res,
                                                       float* __restrict__ C,
                                                       int M, int N, int K, int relu) {
    __shared__ float Ast[16][128];   // [k][m]
    __shared__ float Bsd[16][256];   // [k][2n] duplicated: Bsd[k][2n]=Bsd[k][2n+1]=B[k][n]
    int tid = threadIdx.x;
    int bm = blockIdx.y * 128, bn = blockIdx.x * 128;
    int tx = tid & 15, ty = tid >> 4;
    int m0 = ty * 8, n0 = tx * 8;

    ull acc[4][8];
#pragma unroll
    for (int i = 0; i < 4; i++)
#pragma unroll
        for (int j = 0; j < 8; j++) acc[i][j] = 0ULL;

    for (int kb = 0; kb < K; kb += 16) {
        // A fill: 128 rows x 16 k = 512 float4, 2 per thread (transposed store)
#pragma unroll
        for (int p = 0; p < 2; p++) {
            int idx = tid * 2 + p;
            int row = idx >> 2;
            int kc = (idx & 3) * 4;
            float4 av = *(const float4*)(A + (size_t)(bm + row) * K + kb + kc);
            Ast[kc + 0][row] = av.x;
            Ast[kc + 1][row] = av.y;
            Ast[kc + 2][row] = av.z;
            Ast[kc + 3][row] = av.w;
        }
        // B fill with duplication: 16 k x 128 n = 512 float4 src, 2 per thread
#pragma unroll
        for (int p = 0; p < 2; p++) {
            int idx = tid * 2 + p;
            int bkr = idx >> 5;
            int bc4 = (idx & 31) * 4;
            float4 bv = *(const float4*)(B + (size_t)(kb + bkr) * N + bn + bc4);
            *(float4*)&Bsd[bkr][2 * bc4 + 0] = make_float4(bv.x, bv.x, bv.y, bv.y);
            *(float4*)&Bsd[bkr][2 * bc4 + 4] = make_float4(bv.z, bv.z, bv.w, bv.w);
        }
        __syncthreads();
#pragma unroll
        for (int k = 0; k < 16; k++) {
            // A pairs: (m0+0,m0+1),(m0+2,m0+3),(m0+4,m0+5),(m0+6,m0+7)
            const ull* ap = (const ull*)&Ast[k][m0];
            ull a0 = ap[0], a1 = ap[1], a2 = ap[2], a3 = ap[3];
            // B dup pairs for n0..n0+7
            const ull* bp = (const ull*)&Bsd[k][2 * n0];
            ull b[8];
#pragma unroll
            for (int j = 0; j < 8; j++) b[j] = bp[j];
#pragma unroll
            for (int j = 0; j < 8; j++) {
                fma2(acc[0][j], a0, b[j]);
                fma2(acc[1][j], a1, b[j]);
                fma2(acc[2][j], a2, b[j]);
                fma2(acc[3][j], a3, b[j]);
            }
        }
        __syncthreads();
    }
#pragma unroll
    for (int mp = 0; mp < 4; mp++) {
        int m = bm + m0 + 2 * mp;
#pragma unroll
        for (int j = 0; j < 8; j++) {
            int n = bn + n0 + j;
            float v0 = lo32(acc[mp][j]);
            float v1 = hi32(acc[mp][j]);
            if (bias) { float bv = bias[n]; v0 += bv; v1 += bv; }
            if (res)  { v0 += res[(size_t)m * N + n]; v1 += res[(size_t)(m + 1) * N + n]; }
            if (relu) { v0 = fmaxf(v0, 0.f); v1 = fmaxf(v1, 0.f); }
            C[(size_t)m * N + n] = v0;
            C[(size_t)(m + 1) * N + n] = v1;
        }
    }
}

// ---------------- attention: scores = Q Kt / 8 with causal mask (FFMA2) ----------
__global__ __launch_bounds__(256) void attn_scores_kernel() {
    int kt = blockIdx.x, qt = blockIdx.y, bh = blockIdx.z;
    int b = bh >> 4, hh = bh & 15;
    int tid = threadIdx.x;
    float* sc = g_sc + ((size_t)bh * SS + qt * 64) * SS + kt * 64;
    if (kt > qt) {  // fully masked tile
        for (int i = tid; i < 64 * 64; i += 256)
            sc[(size_t)(i >> 6) * SS + (i & 63)] = -1e30f;
        return;
    }
    __shared__ float Qs[64][66];
    __shared__ float Ks[64][66];
    const float* qb = g_q + ((size_t)(b * SS + qt * 64)) * DD + hh * HD;
    const float* kb = g_k + ((size_t)(b * SS + kt * 64)) * DD + hh * HD;
    for (int i = tid; i < 64 * 64; i += 256) {
        int r = i >> 6, c = i & 63;
        Qs[r][c] = qb[(size_t)r * DD + c];
        Ks[r][c] = kb[(size_t)r * DD + c];
    }
    __syncthreads();
    int tx = tid & 15, ty = tid >> 4;
    int q0 = ty * 4, k0 = tx * 4;
    ull acc[4][4];
#pragma unroll
    for (int i = 0; i < 4; i++)
#pragma unroll
        for (int j = 0; j < 4; j++) acc[i][j] = 0ULL;
#pragma unroll 4
    for (int e2 = 0; e2 < 32; e2++) {
        ull qv[4], kv[4];
#pragma unroll
        for (int i = 0; i < 4; i++) qv[i] = *(const ull*)&Qs[q0 + i][2 * e2];
#pragma unroll
        for (int j = 0; j < 4; j++) kv[j] = *(const ull*)&Ks[k0 + j][2 * e2];
#pragma unroll
        for (int i = 0; i < 4; i++)
#pragma unroll
            for (int j = 0; j < 4; j++) fma2(acc[i][j], qv[i], kv[j]);
    }
    bool diag = (kt == qt);
#pragma unroll
    for (int i = 0; i < 4; i++) {
        int qq = qt * 64 + q0 + i;
#pragma unroll
        for (int j = 0; j < 4; j++) {
            int kk = kt * 64 + k0 + j;
            float v = (lo32(acc[i][j]) + hi32(acc[i][j])) * 0.125f;
            if (diag && kk > qq) v = -1e30f;
            sc[(size_t)(q0 + i) * SS + (k0 + j)] = v;
        }
    }
}

// ---------------- row softmax over S (masked entries are -1e30) ----------------
__global__ __launch_bounds__(256) void softmax_kernel() {
    size_t row = blockIdx.x;
    float* sc = g_sc + row * SS;
    int tid = threadIdx.x;
    float4 v = *(float4*)&sc[tid * 4];
    __shared__ float red[8];
    __shared__ float stat;
    float m = fmaxf(fmaxf(v.x, v.y), fmaxf(v.z, v.w));
    for (int o = 16; o; o >>= 1) m = fmaxf(m, __shfl_down_sync(~0u, m, o));
    if ((tid & 31) == 0) red[tid >> 5] = m;
    __syncthreads();
    if (tid == 0) {
        float t = red[0];
        for (int i = 1; i < 8; i++) t = fmaxf(t, red[i]);
        stat = t;
    }
    __syncthreads();
    float mx = stat;
    float e0 = expf(v.x - mx), e1 = expf(v.y - mx), e2 = expf(v.z - mx), e3 = expf(v.w - mx);
    float s = e0 + e1 + e2 + e3;
    for (int o = 16; o; o >>= 1) s += __shfl_down_sync(~0u, s, o);
    __syncthreads();
    if ((tid & 31) == 0) red[tid >> 5] = s;
    __syncthreads();
    if (tid == 0) {
        float t = 0.f;
        for (int i = 0; i < 8; i++) t += red[i];
        stat = t;
    }
    __syncthreads();
    float inv = 1.0f / stat;
    *(float4*)&sc[tid * 4] = make_float4(e0 * inv, e1 * inv, e2 * inv, e3 * inv);
}

// ---------------- attention: A = P @ V (FFMA2, V transposed in smem) -------------
__global__ __launch_bounds__(256) void attn_av_kernel() {
    int qt = blockIdx.x, bh = blockIdx.y;
    int b = bh >> 4, hh = bh & 15;
    int tid = threadIdx.x;
    __shared__ float Ps[64][66];
    __shared__ float Vt[64][66];   // Vt[e][kk]
    int tx = tid & 15, ty = tid >> 4;
    int q0 = ty * 4, e0 = tx * 4;
    ull acc[4][4];
#pragma unroll
    for (int i = 0; i < 4; i++)
#pragma unroll
        for (int j = 0; j < 4; j++) acc[i][j] = 0ULL;
    const float* scb = g_sc + ((size_t)bh * SS + qt * 64) * SS;
    for (int kt = 0; kt <= qt; kt++) {
        const float* vb = g_v + ((size_t)(b * SS + kt * 64)) * DD + hh * HD;
        for (int i = tid; i < 64 * 64; i += 256) {
            int r = i >> 6, c = i & 63;
            Ps[r][c] = scb[(size_t)r * SS + kt * 64 + c];
            Vt[c][r] = vb[(size_t)r * DD + c];
        }
        __syncthreads();
#pragma unroll 4
        for (int k2 = 0; k2 < 32; k2++) {
            ull pv[4], vv[4];
#pragma unroll
            for (int i = 0; i < 4; i++) pv[i] = *(const ull*)&Ps[q0 + i][2 * k2];
#pragma unroll
            for (int j = 0; j < 4; j++) vv[j] = *(const ull*)&Vt[e0 + j][2 * k2];
#pragma unroll
            for (int i = 0; i < 4; i++)
#pragma unroll
                for (int j = 0; j < 4; j++) fma2(acc[i][j], pv[i], vv[j]);
        }
        __syncthreads();
    }
#pragma unroll
    for (int i = 0; i < 4; i++)
#pragma unroll
        for (int j = 0; j < 4; j++)
            g_a[((size_t)(b * SS + qt * 64 + q0 + i)) * DD + hh * HD + e0 + j] =
                lo32(acc[i][j]) + hi32(acc[i][j]);
}

// ---------------- LayerNorm (row = 1024) ----------------
__global__ __launch_bounds__(256) void ln_kernel(const float* __restrict__ in,
                                                 const float* __restrict__ g,
                                                 const float* __restrict__ bsh,
                                                 float* __restrict__ out) {
    size_t row = blockIdx.x;
    const float* x = in + row * DD;
    int tid = threadIdx.x;
    float4 v = *(const float4*)&x[tid * 4];
    __shared__ float red[8];
    __shared__ float stat;
    float s = v.x + v.y + v.z + v.w;
    for (int o = 16; o; o >>= 1) s += __shfl_down_sync(~0u, s, o);
    if ((tid & 31) == 0) red[tid >> 5] = s;
    __syncthreads();
    if (tid == 0) {
        float t = 0.f;
        for (int i = 0; i < 8; i++) t += red[i];
        stat = t * (1.0f / DD);
    }
    __syncthreads();
    float mu = stat;
    float dx = v.x - mu, dy = v.y - mu, dz = v.z - mu, dw = v.w - mu;
    float ss = dx * dx + dy * dy + dz * dz + dw * dw;
    for (int o = 16; o; o >>= 1) ss += __shfl_down_sync(~0u, ss, o);
    __syncthreads();
    if ((tid & 31) == 0) red[tid >> 5] = ss;
    __syncthreads();
    if (tid == 0) {
        float t = 0.f;
        for (int i = 0; i < 8; i++) t += red[i];
        stat = rsqrtf(t * (1.0f / DD) + 1e-5f);
    }
    __syncthreads();
    float rs = stat;
    float4 gg = *(const float4*)&g[tid * 4];
    float4 bb = *(const float4*)&bsh[tid * 4];
    float4 o4 = make_float4(dx * rs * gg.x + bb.x, dy * rs * gg.y + bb.y,
                            dz * rs * gg.z + bb.z, dw * rs * gg.w + bb.w);
    *(float4*)&out[row * DD + tid * 4] = o4;
}

// ---------------- router head: rlog = zr @ rW2 + rb2 ; argmax ; counters ------
__global__ __launch_bounds__(256) void router2_kernel(const float* __restrict__ rw2,
                                                      const float* __restrict__ rb2) {
    int w = (blockIdx.x * blockDim.x + threadIdx.x) >> 5;
    int lane = threadIdx.x & 31;
    if (w >= MM) return;
    const float* z = g_zr + (size_t)w * RH;
    float s0 = 0.f, s1 = 0.f, s2 = 0.f;
#pragma unroll
    for (int u = 0; u < 4; u++) {
        int j = lane + 32 * u;
        float zv = z[j];
        s0 += zv * rw2[j * 3 + 0];
        s1 += zv * rw2[j * 3 + 1];
        s2 += zv * rw2[j * 3 + 2];
    }
    for (int o = 16; o; o >>= 1) {
        s0 += __shfl_down_sync(~0u, s0, o);
        s1 += __shfl_down_sync(~0u, s1, o);
        s2 += __shfl_down_sync(~0u, s2, o);
    }
    if (lane == 0) {
        s0 += rb2[0]; s1 += rb2[1]; s2 += rb2[2];
        int a = 0; float best = s0;
        if (s1 > best) { best = s1; a = 1; }
        if (s2 > best) { best = s2; a = 2; }
        g_skip[w] = (a == 0);
        atomicAdd(&g_cnt[a], 1);
    }
}

// ---------------- per-token merge: h = skip ? h : ht ----------------
__global__ __launch_bounds__(256) void merge_kernel() {
    int tok = blockIdx.x;
    if (g_skip[tok]) return;
    int tid = threadIdx.x;
    ((float4*)g_h)[(size_t)tok * 256 + tid] = ((float4*)g_ht)[(size_t)tok * 256 + tid];
}

// ---------------- final scalar stats ----------------
__global__ void scalars_kernel(float* out) {
    float fs = (float)g_cnt[0], ff = (float)g_cnt[1], fr = (float)g_cnt[2];
    out[(size_t)MM * VOC + 0] = (ff + fr) / (float)MM;             // effective depth
    out[(size_t)MM * VOC + 1] = fs / (float)(MM * NL);             // skip frac
    out[(size_t)MM * VOC + 2] = ff / (float)(MM * NL);             // fwd frac
    out[(size_t)MM * VOC + 3] = fr / (float)(MM * NL);             // rec frac
}

// ======================= host launch =======================
extern "C" void kernel_launch(void* const* d_in, const int* in_sizes, int n_in,
                              void* d_out, int out_size) {
    const int*   x     = (const int*)d_in[0];
    const float* emb   = (const float*)d_in[1];
    const float* Wq    = (const float*)d_in[2];
    const float* bq    = (const float*)d_in[3];
    const float* Wk    = (const float*)d_in[4];
    const float* bk    = (const float*)d_in[5];
    const float* Wv    = (const float*)d_in[6];
    const float* bv    = (const float*)d_in[7];
    const float* Wo    = (const float*)d_in[8];
    const float* bo    = (const float*)d_in[9];
    const float* ln1g  = (const float*)d_in[10];
    const float* ln1b  = (const float*)d_in[11];
    const float* Wf1   = (const float*)d_in[12];
    const float* bf1   = (const float*)d_in[13];
    const float* Wf2   = (const float*)d_in[14];
    const float* bf2   = (const float*)d_in[15];
    const float* ln2g  = (const float*)d_in[16];
    const float* ln2b  = (const float*)d_in[17];
    const float* rW1   = (const float*)d_in[18];
    const float* rb1   = (const float*)d_in[19];
    const float* rW2   = (const float*)d_in[20];
    const float* rb2   = (const float*)d_in[21];
    const float* Wout  = (const float*)d_in[22];
    const float* bout  = (const float*)d_in[23];
    float* out = (float*)d_out;

    float *h, *h1, *t, *q, *k, *v, *a, *ht, *f1, *zr;
    cudaGetSymbolAddress((void**)&h,  g_h);
    cudaGetSymbolAddress((void**)&h1, g_h1);
    cudaGetSymbolAddress((void**)&t,  g_t);
    cudaGetSymbolAddress((void**)&q,  g_q);
    cudaGetSymbolAddress((void**)&k,  g_k);
    cudaGetSymbolAddress((void**)&v,  g_v);
    cudaGetSymbolAddress((void**)&a,  g_a);
    cudaGetSymbolAddress((void**)&ht, g_ht);
    cudaGetSymbolAddress((void**)&f1, g_f1);
    cudaGetSymbolAddress((void**)&zr, g_zr);

    zero_cnt_kernel<<<1, 32>>>();
    embed_kernel<<<MM, 256>>>(x, emb);

    for (int l = 0; l < NL; l++) {
        // router
        sgemm_kernel<<<dim3(RH / 128, MM / 128), 256>>>(
            h, rW1 + (size_t)l * DD * RH, rb1 + l * RH, nullptr, zr, MM, RH, DD, 1);
        router2_kernel<<<MM / 8, 256>>>(rW2 + (size_t)l * RH * 3, rb2 + l * 3);
        // QKV
        sgemm_kernel<<<dim3(DD / 128, MM / 128), 256>>>(h, Wq, bq, nullptr, q, MM, DD, DD, 0);
        sgemm_kernel<<<dim3(DD / 128, MM / 128), 256>>>(h, Wk, bk, nullptr, k, MM, DD, DD, 0);
        sgemm_kernel<<<dim3(DD / 128, MM / 128), 256>>>(h, Wv, bv, nullptr, v, MM, DD, DD, 0);
        // attention
        attn_scores_kernel<<<dim3(SS / 64, SS / 64, BHT), 256>>>();
        softmax_kernel<<<BHT * SS, 256>>>();
        attn_av_kernel<<<dim3(SS / 64, BHT), 256>>>();
        // O-proj + residual, LN1
        sgemm_kernel<<<dim3(DD / 128, MM / 128), 256>>>(a, Wo, bo, h, t, MM, DD, DD, 0);
        ln_kernel<<<MM, 256>>>(t, ln1g, ln1b, h1);
        // FFN + residual, LN2
        sgemm_kernel<<<dim3(DFF / 128, MM / 128), 256>>>(h1, Wf1, bf1, nullptr, f1, MM, DFF, DD, 1);
        sgemm_kernel<<<dim3(DD / 128, MM / 128), 256>>>(f1, Wf2, bf2, h1, t, MM, DD, DFF, 0);
        ln_kernel<<<MM, 256>>>(t, ln2g, ln2b, ht);
        // per-token skip merge
        merge_kernel<<<MM, 256>>>();
    }

    // logits
    sgemm_kernel<<<dim3(VOC / 128, MM / 128), 256>>>(h, Wout, bout, nullptr, out, MM, VOC, DD, 0);
    scalars_kernel<<<1, 1>>>(out);
}

// round 5
// speedup vs baseline: 3.0812x; 3.0812x over previous
#include <cuda_runtime.h>
#include <math.h>
#include <stdint.h>

#define BB 2
#define SS 1024
#define DD 1024
#define NH 16
#define HD 64
#define NL 12
#define DFF 4096
#define RH 128
#define VOC 32000
#define MM (BB*SS)
#define BHT (BB*NH)
#define QKVS 3072

// ---- static scratch ----
__device__ float g_h [MM*DD];
__device__ float g_h1[MM*DD];
__device__ float g_t [MM*DD];
__device__ float g_qkv[MM*QKVS];
__device__ float g_a [MM*DD];
__device__ float g_ht[MM*DD];
__device__ float g_f1[MM*DFF];
__device__ float g_zr[MM*RH];
__device__ float g_sc[(size_t)BHT*SS*SS];
__device__ unsigned char g_skip[MM];
__device__ int g_cnt[3];
__device__ float g_wqkv_h[(size_t)QKVS*DD], g_wqkv_l[(size_t)QKVS*DD];
__device__ float g_wo_h[(size_t)DD*DD],     g_wo_l[(size_t)DD*DD];
__device__ float g_wf1_h[(size_t)DFF*DD],   g_wf1_l[(size_t)DFF*DD];
__device__ float g_wf2_h[(size_t)DD*DFF],   g_wf2_l[(size_t)DD*DFF];
__device__ float g_wout_h[(size_t)VOC*DD],  g_wout_l[(size_t)VOC*DD];
__device__ float g_bqkv[QKVS];

static __device__ __forceinline__ unsigned smem_u32(const void* p) {
    unsigned r;
    asm("{ .reg .u64 t; cvta.to.shared.u64 t, %1; cvt.u32.u64 %0, t; }" : "=r"(r) : "l"(p));
    return r;
}
static __device__ __forceinline__ float to_tf32f(float x) {
    float r; asm("cvt.rna.tf32.f32 %0, %1;" : "=f"(r) : "f"(x)); return r;
}
static __device__ __forceinline__ void mma8(float* c, const unsigned* a, const unsigned* b) {
    asm volatile(
        "mma.sync.aligned.m16n8k8.row.col.f32.tf32.tf32.f32 "
        "{%0,%1,%2,%3}, {%4,%5,%6,%7}, {%8,%9}, {%0,%1,%2,%3};"
        : "+f"(c[0]), "+f"(c[1]), "+f"(c[2]), "+f"(c[3])
        : "r"(a[0]), "r"(a[1]), "r"(a[2]), "r"(a[3]), "r"(b[0]), "r"(b[1]));
}
#define CP16(dst, src) \
    asm volatile("cp.async.cg.shared.global [%0], [%1], 16;" :: "r"(dst), "l"(src))

__global__ void zero_cnt_kernel() { if (threadIdx.x < 3) g_cnt[threadIdx.x] = 0; }

// W[K][N] -> Th/Tl [N][K] with tf32 hi/lo split
__global__ __launch_bounds__(256) void wtrans_kernel(const float* __restrict__ W,
                                                     float* __restrict__ Th,
                                                     float* __restrict__ Tl, int K, int N) {
    __shared__ float tile[32][33];
    int n0 = blockIdx.x * 32, k0 = blockIdx.y * 32;
    int tx = threadIdx.x & 31, ty = threadIdx.x >> 5;
    for (int i = ty; i < 32; i += 8) tile[i][tx] = W[(size_t)(k0 + i) * N + n0 + tx];
    __syncthreads();
    for (int i = ty; i < 32; i += 8) {
        float v = tile[tx][i];
        float hv = to_tf32f(v);
        float lv = to_tf32f(v - hv);
        size_t o = (size_t)(n0 + i) * K + k0 + tx;
        Th[o] = hv; Tl[o] = lv;
    }
}

__global__ void bcat_kernel(const float* __restrict__ bq, const float* __restrict__ bk,
                            const float* __restrict__ bv) {
    int i = blockIdx.x * 256 + threadIdx.x;
    g_bqkv[i] = (i < 1024) ? bq[i] : (i < 2048) ? bk[i - 1024] : bv[i - 2048];
}

__global__ __launch_bounds__(256) void embed_kernel(const int* __restrict__ x,
                                                    const float* __restrict__ emb) {
    int tok = blockIdx.x, s = tok % SS, id = x[tok];
    int d0 = threadIdx.x * 4;
    float4 ev = *(const float4*)(emb + (size_t)id * DD + d0);
    float o[4] = {ev.x, ev.y, ev.z, ev.w};
#pragma unroll
    for (int j = 0; j < 4; j++) {
        int d = d0 + j;
        float ang = (float)s * expf((float)(d & ~1) * (-9.210340371976184f / 1024.0f));
        o[j] = o[j] * 32.0f + ((d & 1) ? cosf(ang) : sinf(ang));
    }
    *(float4*)(g_h + (size_t)tok * DD + d0) = make_float4(o[0], o[1], o[2], o[3]);
}

// ===== mma.sync 3xTF32 GEMM: C[M,N] = [res+] A[M,K]@B + bias [relu]
// B pre-transposed+split: Bh/Bl are [N][K]. CTA tile 128x128, warp 32x64, K chunk 16.
#define KCH 16
#define ROWW 20                     // padded row stride (floats) for conflict-free frags
#define MATB (128*ROWW*4)           // 10240 bytes per matrix per stage
#define STGB (3*MATB)               // A | Bh | Bl
#define TGSM (3*STGB)               // 3 stages = 92160

__global__ __launch_bounds__(256)
void tgemm_kernel(const float* __restrict__ A, const float* __restrict__ Bh,
                  const float* __restrict__ Bl, const float* __restrict__ bias,
                  const float* __restrict__ res, float* __restrict__ C,
                  int M, int N, int K, int relu) {
    extern __shared__ char smem[];
    unsigned sb = smem_u32(smem);
    int tid = threadIdx.x, wid = tid >> 5, lane = tid & 31;
    int grp = lane >> 2, qid = lane & 3;
    int bm = blockIdx.y * 128, bn = blockIdx.x * 128;
    int wm0 = (wid & 3) * 32, wn0 = (wid >> 2) * 64;

    float acc[2][8][4];
#pragma unroll
    for (int mt = 0; mt < 2; mt++)
#pragma unroll
        for (int nt = 0; nt < 8; nt++)
#pragma unroll
            for (int e = 0; e < 4; e++) acc[mt][nt][e] = 0.f;

    int nchunks = K / KCH;
    int r0 = tid >> 2, kc0 = (tid & 3) * 16;          // chunk copy coords (16B units)
    int r1 = (tid + 256) >> 2, kc1 = ((tid + 256) & 3) * 16;

    // prologue: issue stages 0,1
#pragma unroll
    for (int c = 0; c < 2; c++) {
        int kb = c * KCH;
        unsigned st = sb + (c % 3) * STGB;
        CP16(st + r0 * 80 + kc0, A + (size_t)(bm + r0) * K + kb + kc0 / 4);
        CP16(st + r1 * 80 + kc1, A + (size_t)(bm + r1) * K + kb + kc1 / 4);
        CP16(st + MATB + r0 * 80 + kc0, Bh + (size_t)(bn + r0) * K + kb + kc0 / 4);
        CP16(st + MATB + r1 * 80 + kc1, Bh + (size_t)(bn + r1) * K + kb + kc1 / 4);
        CP16(st + 2 * MATB + r0 * 80 + kc0, Bl + (size_t)(bn + r0) * K + kb + kc0 / 4);
        CP16(st + 2 * MATB + r1 * 80 + kc1, Bl + (size_t)(bn + r1) * K + kb + kc1 / 4);
        asm volatile("cp.async.commit_group;");
    }

    for (int c = 0; c < nchunks; c++) {
        if (c + 2 < nchunks) asm volatile("cp.async.wait_group 1;");
        else                 asm volatile("cp.async.wait_group 0;");
        __syncthreads();
        const float* As  = (const float*)(smem + (c % 3) * STGB);
        const float* Bhs = As + 128 * ROWW;
        const float* Bls = Bhs + 128 * ROWW;
#pragma unroll
        for (int s8 = 0; s8 < 2; s8++) {
            int k8 = s8 * 8;
            unsigned Ah[2][4], Al[2][4];
#pragma unroll
            for (int mt = 0; mt < 2; mt++) {
                int ra = wm0 + mt * 16 + grp;
                float x0 = As[ra * ROWW + k8 + qid];
                float x1 = As[(ra + 8) * ROWW + k8 + qid];
                float x2 = As[ra * ROWW + k8 + qid + 4];
                float x3 = As[(ra + 8) * ROWW + k8 + qid + 4];
                float h0 = to_tf32f(x0), h1 = to_tf32f(x1), h2 = to_tf32f(x2), h3 = to_tf32f(x3);
                Ah[mt][0] = __float_as_uint(h0); Ah[mt][1] = __float_as_uint(h1);
                Ah[mt][2] = __float_as_uint(h2); Ah[mt][3] = __float_as_uint(h3);
                Al[mt][0] = __float_as_uint(to_tf32f(x0 - h0));
                Al[mt][1] = __float_as_uint(to_tf32f(x1 - h1));
                Al[mt][2] = __float_as_uint(to_tf32f(x2 - h2));
                Al[mt][3] = __float_as_uint(to_tf32f(x3 - h3));
            }
#pragma unroll
            for (int nt = 0; nt < 8; nt++) {
                int nr = wn0 + nt * 8 + grp;
                unsigned bh[2], bl[2];
                bh[0] = __float_as_uint(Bhs[nr * ROWW + k8 + qid]);
                bh[1] = __float_as_uint(Bhs[nr * ROWW + k8 + qid + 4]);
                bl[0] = __float_as_uint(Bls[nr * ROWW + k8 + qid]);
                bl[1] = __float_as_uint(Bls[nr * ROWW + k8 + qid + 4]);
#pragma unroll
                for (int mt = 0; mt < 2; mt++) {
                    mma8(acc[mt][nt], Ah[mt], bh);
                    mma8(acc[mt][nt], Ah[mt], bl);
                    mma8(acc[mt][nt], Al[mt], bh);
                }
            }
        }
        __syncthreads();
        if (c + 2 < nchunks) {
            int kb = (c + 2) * KCH;
            unsigned st = sb + ((c + 2) % 3) * STGB;
            CP16(st + r0 * 80 + kc0, A + (size_t)(bm + r0) * K + kb + kc0 / 4);
            CP16(st + r1 * 80 + kc1, A + (size_t)(bm + r1) * K + kb + kc1 / 4);
            CP16(st + MATB + r0 * 80 + kc0, Bh + (size_t)(bn + r0) * K + kb + kc0 / 4);
            CP16(st + MATB + r1 * 80 + kc1, Bh + (size_t)(bn + r1) * K + kb + kc1 / 4);
            CP16(st + 2 * MATB + r0 * 80 + kc0, Bl + (size_t)(bn + r0) * K + kb + kc0 / 4);
            CP16(st + 2 * MATB + r1 * 80 + kc1, Bl + (size_t)(bn + r1) * K + kb + kc1 / 4);
            asm volatile("cp.async.commit_group;");
        }
    }

    // epilogue
#pragma unroll
    for (int mt = 0; mt < 2; mt++) {
#pragma unroll
        for (int nt = 0; nt < 8; nt++) {
            int row0 = bm + wm0 + mt * 16 + grp;
            int col = bn + wn0 + nt * 8 + 2 * qid;
            float2 v0 = make_float2(acc[mt][nt][0], acc[mt][nt][1]);
            float2 v1 = make_float2(acc[mt][nt][2], acc[mt][nt][3]);
            if (bias) {
                float2 bv = *(const float2*)(bias + col);
                v0.x += bv.x; v0.y += bv.y; v1.x += bv.x; v1.y += bv.y;
            }
            if (res) {
                float2 ra = *(const float2*)(res + (size_t)row0 * N + col);
                float2 rb = *(const float2*)(res + (size_t)(row0 + 8) * N + col);
                v0.x += ra.x; v0.y += ra.y; v1.x += rb.x; v1.y += rb.y;
            }
            if (relu) {
                v0.x = fmaxf(v0.x, 0.f); v0.y = fmaxf(v0.y, 0.f);
                v1.x = fmaxf(v1.x, 0.f); v1.y = fmaxf(v1.y, 0.f);
            }
            *(float2*)(C + (size_t)row0 * N + col) = v0;
            *(float2*)(C + (size_t)(row0 + 8) * N + col) = v1;
        }
    }
}

// ===== SIMT SGEMM (router GEMM1 only, N=128) =====
__global__ __launch_bounds__(256) void sgemm_kernel(const float* __restrict__ A,
                                                    const float* __restrict__ B,
                                                    const float* __restrict__ bias,
                                                    float* __restrict__ C,
                                                    int M, int N, int K) {
    __shared__ float Ast[16][128];
    __shared__ float Bs[16][64];
    int tid = threadIdx.x;
    int bm = blockIdx.y * 128, bn = blockIdx.x * 64;
    int tx = tid & 15, ty = tid >> 4;
    int m0 = ty * 8, n0 = tx * 4;
    float acc[8][4];
#pragma unroll
    for (int i = 0; i < 8; i++)
#pragma unroll
        for (int j = 0; j < 4; j++) acc[i][j] = 0.f;
    int arow = tid >> 2, ak4 = (tid & 3) * 4, bk = tid >> 4, bc4 = (tid & 15) * 4;
    for (int kb = 0; kb < K; kb += 16) {
#pragma unroll
        for (int p = 0; p < 2; p++) {
            int r = arow + p * 64;
            float4 av = *(const float4*)(A + (size_t)(bm + r) * K + kb + ak4);
            Ast[ak4+0][r] = av.x; Ast[ak4+1][r] = av.y; Ast[ak4+2][r] = av.z; Ast[ak4+3][r] = av.w;
        }
        *(float4*)&Bs[bk][bc4] = *(const float4*)(B + (size_t)(kb + bk) * N + bn + bc4);
        __syncthreads();
#pragma unroll
        for (int k = 0; k < 16; k++) {
            float4 a0 = *(float4*)&Ast[k][m0];
            float4 a1 = *(float4*)&Ast[k][m0 + 4];
            float4 bv = *(float4*)&Bs[k][n0];
            float am[8] = {a0.x,a0.y,a0.z,a0.w,a1.x,a1.y,a1.z,a1.w};
            float bb[4] = {bv.x,bv.y,bv.z,bv.w};
#pragma unroll
            for (int i = 0; i < 8; i++)
#pragma unroll
                for (int j = 0; j < 4; j++) acc[i][j] += am[i] * bb[j];
        }
        __syncthreads();
    }
#pragma unroll
    for (int i = 0; i < 8; i++)
#pragma unroll
        for (int j = 0; j < 4; j++) {
            float v = acc[i][j] + bias[bn + n0 + j];
            C[(size_t)(bm + m0 + i) * N + bn + n0 + j] = fmaxf(v, 0.f);
        }
}

// ===== attention (fp32 SIMT) =====
__global__ __launch_bounds__(256) void attn_scores_kernel() {
    int kt = blockIdx.x, qt = blockIdx.y, bh = blockIdx.z;
    int b = bh >> 4, hh = bh & 15;
    int tid = threadIdx.x;
    float* sc = g_sc + ((size_t)bh * SS + qt * 64) * SS + kt * 64;
    if (kt > qt) {
        for (int i = tid; i < 64 * 64; i += 256)
            sc[(size_t)(i >> 6) * SS + (i & 63)] = -1e30f;
        return;
    }
    __shared__ float Qs[64][65];
    __shared__ float Ks[64][65];
    const float* qb = g_qkv + ((size_t)(b * SS + qt * 64)) * QKVS + hh * HD;
    const float* kb = g_qkv + ((size_t)(b * SS + kt * 64)) * QKVS + 1024 + hh * HD;
    for (int i = tid; i < 64 * 64; i += 256) {
        int r = i >> 6, c = i & 63;
        Qs[r][c] = qb[(size_t)r * QKVS + c];
        Ks[r][c] = kb[(size_t)r * QKVS + c];
    }
    __syncthreads();
    int tx = tid & 15, ty = tid >> 4;
    int q0 = ty * 4, k0 = tx * 4;
    float acc[4][4];
#pragma unroll
    for (int i = 0; i < 4; i++)
#pragma unroll
        for (int j = 0; j < 4; j++) acc[i][j] = 0.f;
    for (int e = 0; e < 64; e++) {
        float qv[4], kv[4];
#pragma unroll
        for (int i = 0; i < 4; i++) qv[i] = Qs[q0 + i][e];
#pragma unroll
        for (int j = 0; j < 4; j++) kv[j] = Ks[k0 + j][e];
#pragma unroll
        for (int i = 0; i < 4; i++)
#pragma unroll
            for (int j = 0; j < 4; j++) acc[i][j] += qv[i] * kv[j];
    }
    bool diag = (kt == qt);
#pragma unroll
    for (int i = 0; i < 4; i++) {
        int qq = qt * 64 + q0 + i;
#pragma unroll
        for (int j = 0; j < 4; j++) {
            int kk = kt * 64 + k0 + j;
            float v = acc[i][j] * 0.125f;
            if (diag && kk > qq) v = -1e30f;
            sc[(size_t)(q0 + i) * SS + (k0 + j)] = v;
        }
    }
}

__global__ __launch_bounds__(256) void softmax_kernel() {
    size_t row = blockIdx.x;
    float* sc = g_sc + row * SS;
    int tid = threadIdx.x;
    float4 v = *(float4*)&sc[tid * 4];
    __shared__ float red[8];
    __shared__ float stat;
    float m = fmaxf(fmaxf(v.x, v.y), fmaxf(v.z, v.w));
    for (int o = 16; o; o >>= 1) m = fmaxf(m, __shfl_down_sync(~0u, m, o));
    if ((tid & 31) == 0) red[tid >> 5] = m;
    __syncthreads();
    if (tid == 0) {
        float t = red[0];
        for (int i = 1; i < 8; i++) t = fmaxf(t, red[i]);
        stat = t;
    }
    __syncthreads();
    float mx = stat;
    float e0 = expf(v.x - mx), e1 = expf(v.y - mx), e2 = expf(v.z - mx), e3 = expf(v.w - mx);
    float s = e0 + e1 + e2 + e3;
    for (int o = 16; o; o >>= 1) s += __shfl_down_sync(~0u, s, o);
    __syncthreads();
    if ((tid & 31) == 0) red[tid >> 5] = s;
    __syncthreads();
    if (tid == 0) {
        float t = 0.f;
        for (int i = 0; i < 8; i++) t += red[i];
        stat = t;
    }
    __syncthreads();
    float inv = 1.0f / stat;
    *(float4*)&sc[tid * 4] = make_float4(e0 * inv, e1 * inv, e2 * inv, e3 * inv);
}

__global__ __launch_bounds__(256) void attn_av_kernel() {
    int qt = blockIdx.x, bh = blockIdx.y;
    int b = bh >> 4, hh = bh & 15;
    int tid = threadIdx.x;
    __shared__ float Ps[64][65];
    __shared__ float Vs[64][65];
    int tx = tid & 15, ty = tid >> 4;
    int q0 = ty * 4, e0 = tx * 4;
    float acc[4][4];
#pragma unroll
    for (int i = 0; i < 4; i++)
#pragma unroll
        for (int j = 0; j < 4; j++) acc[i][j] = 0.f;
    const float* scb = g_sc + ((size_t)bh * SS + qt * 64) * SS;
    for (int kt = 0; kt <= qt; kt++) {
        const float* vb = g_qkv + ((size_t)(b * SS + kt * 64)) * QKVS + 2048 + hh * HD;
        for (int i = tid; i < 64 * 64; i += 256) {
            int r = i >> 6, c = i & 63;
            Ps[r][c] = scb[(size_t)r * SS + kt * 64 + c];
            Vs[r][c] = vb[(size_t)r * QKVS + c];
        }
        __syncthreads();
        for (int kk = 0; kk < 64; kk++) {
            float pv[4], vv[4];
#pragma unroll
            for (int i = 0; i < 4; i++) pv[i] = Ps[q0 + i][kk];
#pragma unroll
            for (int j = 0; j < 4; j++) vv[j] = Vs[kk][e0 + j];
#pragma unroll
            for (int i = 0; i < 4; i++)
#pragma unroll
                for (int j = 0; j < 4; j++) acc[i][j] += pv[i] * vv[j];
        }
        __syncthreads();
    }
#pragma unroll
    for (int i = 0; i < 4; i++)
#pragma unroll
        for (int j = 0; j < 4; j++)
            g_a[((size_t)(b * SS + qt * 64 + q0 + i)) * DD + hh * HD + e0 + j] = acc[i][j];
}

__global__ __launch_bounds__(256) void ln_kernel(const float* __restrict__ in,
                                                 const float* __restrict__ g,
                                                 const float* __restrict__ bsh,
                                                 float* __restrict__ out) {
    size_t row = blockIdx.x;
    const float* x = in + row * DD;
    int tid = threadIdx.x;
    float4 v = *(const float4*)&x[tid * 4];
    __shared__ float red[8];
    __shared__ float stat;
    float s = v.x + v.y + v.z + v.w;
    for (int o = 16; o; o >>= 1) s += __shfl_down_sync(~0u, s, o);
    if ((tid & 31) == 0) red[tid >> 5] = s;
    __syncthreads();
    if (tid == 0) {
        float t = 0.f;
        for (int i = 0; i < 8; i++) t += red[i];
        stat = t * (1.0f / DD);
    }
    __syncthreads();
    float mu = stat;
    float dx = v.x - mu, dy = v.y - mu, dz = v.z - mu, dw = v.w - mu;
    float ss = dx * dx + dy * dy + dz * dz + dw * dw;
    for (int o = 16; o; o >>= 1) ss += __shfl_down_sync(~0u, ss, o);
    __syncthreads();
    if ((tid & 31) == 0) red[tid >> 5] = ss;
    __syncthreads();
    if (tid == 0) {
        float t = 0.f;
        for (int i = 0; i < 8; i++) t += red[i];
        stat = rsqrtf(t * (1.0f / DD) + 1e-5f);
    }
    __syncthreads();
    float rs = stat;
    float4 gg = *(const float4*)&g[tid * 4];
    float4 bb = *(const float4*)&bsh[tid * 4];
    *(float4*)&out[row * DD + tid * 4] =
        make_float4(dx * rs * gg.x + bb.x, dy * rs * gg.y + bb.y,
                    dz * rs * gg.z + bb.z, dw * rs * gg.w + bb.w);
}

__global__ __launch_bounds__(256) void router2_kernel(const float* __restrict__ rw2,
                                                      const float* __restrict__ rb2) {
    int w = (blockIdx.x * blockDim.x + threadIdx.x) >> 5;
    int lane = threadIdx.x & 31;
    if (w >= MM) return;
    const float* z = g_zr + (size_t)w * RH;
    float s0 = 0.f, s1 = 0.f, s2 = 0.f;
#pragma unroll
    for (int u = 0; u < 4; u++) {
        int j = lane + 32 * u;
        float zv = z[j];
        s0 += zv * rw2[j * 3 + 0];
        s1 += zv * rw2[j * 3 + 1];
        s2 += zv * rw2[j * 3 + 2];
    }
    for (int o = 16; o; o >>= 1) {
        s0 += __shfl_down_sync(~0u, s0, o);
        s1 += __shfl_down_sync(~0u, s1, o);
        s2 += __shfl_down_sync(~0u, s2, o);
    }
    if (lane == 0) {
        s0 += rb2[0]; s1 += rb2[1]; s2 += rb2[2];
        int a = 0; float best = s0;
        if (s1 > best) { best = s1; a = 1; }
        if (s2 > best) { best = s2; a = 2; }
        g_skip[w] = (a == 0);
        atomicAdd(&g_cnt[a], 1);
    }
}

__global__ __launch_bounds__(256) void merge_kernel() {
    int tok = blockIdx.x;
    if (g_skip[tok]) return;
    ((float4*)g_h)[(size_t)tok * 256 + threadIdx.x] =
        ((float4*)g_ht)[(size_t)tok * 256 + threadIdx.x];
}

__global__ void scalars_kernel(float* out) {
    float fs = (float)g_cnt[0], ff = (float)g_cnt[1], fr = (float)g_cnt[2];
    out[(size_t)MM * VOC + 0] = (ff + fr) / (float)MM;
    out[(size_t)MM * VOC + 1] = fs / (float)(MM * NL);
    out[(size_t)MM * VOC + 2] = ff / (float)(MM * NL);
    out[(size_t)MM * VOC + 3] = fr / (float)(MM * NL);
}

extern "C" void kernel_launch(void* const* d_in, const int* in_sizes, int n_in,
                              void* d_out, int out_size) {
    const int*   x    = (const int*)d_in[0];
    const float* emb  = (const float*)d_in[1];
    const float* Wq   = (const float*)d_in[2];
    const float* bq   = (const float*)d_in[3];
    const float* Wk   = (const float*)d_in[4];
    const float* bk   = (const float*)d_in[5];
    const float* Wv   = (const float*)d_in[6];
    const float* bv   = (const float*)d_in[7];
    const float* Wo   = (const float*)d_in[8];
    const float* bo   = (const float*)d_in[9];
    const float* ln1g = (const float*)d_in[10];
    const float* ln1b = (const float*)d_in[11];
    const float* Wf1  = (const float*)d_in[12];
    const float* bf1  = (const float*)d_in[13];
    const float* Wf2  = (const float*)d_in[14];
    const float* bf2  = (const float*)d_in[15];
    const float* ln2g = (const float*)d_in[16];
    const float* ln2b = (const float*)d_in[17];
    const float* rW1  = (const float*)d_in[18];
    const float* rb1  = (const float*)d_in[19];
    const float* rW2  = (const float*)d_in[20];
    const float* rb2  = (const float*)d_in[21];
    const float* Wout = (const float*)d_in[22];
    const float* bout = (const float*)d_in[23];
    float* out = (float*)d_out;

    cudaFuncSetAttribute(tgemm_kernel, cudaFuncAttributeMaxDynamicSharedMemorySize, TGSM);

    float *h, *h1, *t, *qkv, *a, *ht, *f1, *zr;
    float *wqh, *wql, *woh, *wol, *w1h, *w1l, *w2h, *w2l, *wvh, *wvl, *bqkv;
    cudaGetSymbolAddress((void**)&h, g_h);
    cudaGetSymbolAddress((void**)&h1, g_h1);
    cudaGetSymbolAddress((void**)&t, g_t);
    cudaGetSymbolAddress((void**)&qkv, g_qkv);
    cudaGetSymbolAddress((void**)&a, g_a);
    cudaGetSymbolAddress((void**)&ht, g_ht);
    cudaGetSymbolAddress((void**)&f1, g_f1);
    cudaGetSymbolAddress((void**)&zr, g_zr);
    cudaGetSymbolAddress((void**)&wqh, g_wqkv_h);
    cudaGetSymbolAddress((void**)&wql, g_wqkv_l);
    cudaGetSymbolAddress((void**)&woh, g_wo_h);
    cudaGetSymbolAddress((void**)&wol, g_wo_l);
    cudaGetSymbolAddress((void**)&w1h, g_wf1_h);
    cudaGetSymbolAddress((void**)&w1l, g_wf1_l);
    cudaGetSymbolAddress((void**)&w2h, g_wf2_h);
    cudaGetSymbolAddress((void**)&w2l, g_wf2_l);
    cudaGetSymbolAddress((void**)&wvh, g_wout_h);
    cudaGetSymbolAddress((void**)&wvl, g_wout_l);
    cudaGetSymbolAddress((void**)&bqkv, g_bqkv);

    // weight preprocessing (deterministic, every launch)
    wtrans_kernel<<<dim3(DD/32, DD/32), 256>>>(Wq, wqh, wql, DD, DD);
    wtrans_kernel<<<dim3(DD/32, DD/32), 256>>>(Wk, wqh + (size_t)1024*DD, wql + (size_t)1024*DD, DD, DD);
    wtrans_kernel<<<dim3(DD/32, DD/32), 256>>>(Wv, wqh + (size_t)2048*DD, wql + (size_t)2048*DD, DD, DD);
    wtrans_kernel<<<dim3(DD/32, DD/32), 256>>>(Wo, woh, wol, DD, DD);
    wtrans_kernel<<<dim3(DFF/32, DD/32), 256>>>(Wf1, w1h, w1l, DD, DFF);
    wtrans_kernel<<<dim3(DD/32, DFF/32), 256>>>(Wf2, w2h, w2l, DFF, DD);
    wtrans_kernel<<<dim3(VOC/32, DD/32), 256>>>(Wout, wvh, wvl, DD, VOC);
    bcat_kernel<<<QKVS/256, 256>>>(bq, bk, bv);

    zero_cnt_kernel<<<1, 32>>>();
    embed_kernel<<<MM, 256>>>(x, emb);

    for (int l = 0; l < NL; l++) {
        sgemm_kernel<<<dim3(RH/64, MM/128), 256>>>(h, rW1 + (size_t)l*DD*RH, rb1 + l*RH, zr, MM, RH, DD);
        router2_kernel<<<MM/8, 256>>>(rW2 + (size_t)l*RH*3, rb2 + l*3);
        tgemm_kernel<<<dim3(QKVS/128, MM/128), 256, TGSM>>>(h, wqh, wql, bqkv, nullptr, qkv, MM, QKVS, DD, 0);
        attn_scores_kernel<<<dim3(SS/64, SS/64, BHT), 256>>>();
        softmax_kernel<<<BHT*SS, 256>>>();
        attn_av_kernel<<<dim3(SS/64, BHT), 256>>>();
        tgemm_kernel<<<dim3(DD/128, MM/128), 256, TGSM>>>(a, woh, wol, bo, h, t, MM, DD, DD, 0);
        ln_kernel<<<MM, 256>>>(t, ln1g, ln1b, h1);
        tgemm_kernel<<<dim3(DFF/128, MM/128), 256, TGSM>>>(h1, w1h, w1l, bf1, nullptr, f1, MM, DFF, DD, 1);
        tgemm_kernel<<<dim3(DD/128, MM/128), 256, TGSM>>>(f1, w2h, w2l, bf2, h1, t, MM, DD, DFF, 0);
        ln_kernel<<<MM, 256>>>(t, ln2g, ln2b, ht);
        merge_kernel<<<MM, 256>>>();
    }

    tgemm_kernel<<<dim3(VOC/128, MM/128), 256, TGSM>>>(h, wvh, wvl, bout, nullptr, out, MM, VOC, DD, 0);
    scalars_kernel<<<1, 1>>>(out);
}

// round 6
// speedup vs baseline: 3.5294x; 1.1455x over previous
#include <cuda_runtime.h>
#include <math.h>
#include <stdint.h>

#define BB 2
#define SS 1024
#define DD 1024
#define NH 16
#define HD 64
#define NL 12
#define DFF 4096
#define RH 128
#define VOC 32000
#define MM (BB*SS)
#define BHT (BB*NH)
#define QKVS 3072

// ---- static scratch ----
__device__ float g_h [MM*DD];
__device__ float g_h1[MM*DD];
__device__ float g_t [MM*DD];
__device__ float g_qkv[MM*QKVS];
__device__ float g_a [MM*DD];
__device__ float g_ht[MM*DD];
__device__ float g_f1[MM*DFF];
__device__ float g_zr[MM*RH];
__device__ float g_sc[(size_t)BHT*SS*SS];
__device__ unsigned char g_skip[MM];
__device__ int g_cnt[3];
__device__ float g_wqkv_h[(size_t)QKVS*DD], g_wqkv_l[(size_t)QKVS*DD];
__device__ float g_wo_h[(size_t)DD*DD],     g_wo_l[(size_t)DD*DD];
__device__ float g_wf1_h[(size_t)DFF*DD],   g_wf1_l[(size_t)DFF*DD];
__device__ float g_wf2_h[(size_t)DD*DFF],   g_wf2_l[(size_t)DD*DFF];
__device__ float g_wout_h[(size_t)VOC*DD],  g_wout_l[(size_t)VOC*DD];
__device__ float g_bqkv[QKVS];

static __device__ __forceinline__ unsigned smem_u32(const void* p) {
    unsigned r;
    asm("{ .reg .u64 t; cvta.to.shared.u64 t, %1; cvt.u32.u64 %0, t; }" : "=r"(r) : "l"(p));
    return r;
}
static __device__ __forceinline__ float to_tf32f(float x) {
    float r; asm("cvt.rna.tf32.f32 %0, %1;" : "=f"(r) : "f"(x)); return r;
}
static __device__ __forceinline__ void mma8(float* c, const unsigned* a, const unsigned* b) {
    asm volatile(
        "mma.sync.aligned.m16n8k8.row.col.f32.tf32.tf32.f32 "
        "{%0,%1,%2,%3}, {%4,%5,%6,%7}, {%8,%9}, {%0,%1,%2,%3};"
        : "+f"(c[0]), "+f"(c[1]), "+f"(c[2]), "+f"(c[3])
        : "r"(a[0]), "r"(a[1]), "r"(a[2]), "r"(a[3]), "r"(b[0]), "r"(b[1]));
}
static __device__ __forceinline__ float4 hi4(float4 v) {
    return make_float4(to_tf32f(v.x), to_tf32f(v.y), to_tf32f(v.z), to_tf32f(v.w));
}
static __device__ __forceinline__ float4 lo4(float4 v, float4 h) {
    return make_float4(to_tf32f(v.x - h.x), to_tf32f(v.y - h.y),
                       to_tf32f(v.z - h.z), to_tf32f(v.w - h.w));
}
#define CP16(dst, src) \
    asm volatile("cp.async.cg.shared.global [%0], [%1], 16;" :: "r"(dst), "l"(src))

__global__ void zero_cnt_kernel() { if (threadIdx.x < 3) g_cnt[threadIdx.x] = 0; }

// W[K][N] -> Th/Tl [N][K] with tf32 hi/lo split
__global__ __launch_bounds__(256) void wtrans_kernel(const float* __restrict__ W,
                                                     float* __restrict__ Th,
                                                     float* __restrict__ Tl, int K, int N) {
    __shared__ float tile[32][33];
    int n0 = blockIdx.x * 32, k0 = blockIdx.y * 32;
    int tx = threadIdx.x & 31, ty = threadIdx.x >> 5;
    for (int i = ty; i < 32; i += 8) tile[i][tx] = W[(size_t)(k0 + i) * N + n0 + tx];
    __syncthreads();
    for (int i = ty; i < 32; i += 8) {
        float v = tile[tx][i];
        float hv = to_tf32f(v);
        float lv = to_tf32f(v - hv);
        size_t o = (size_t)(n0 + i) * K + k0 + tx;
        Th[o] = hv; Tl[o] = lv;
    }
}

__global__ void bcat_kernel(const float* __restrict__ bq, const float* __restrict__ bk,
                            const float* __restrict__ bv) {
    int i = blockIdx.x * 256 + threadIdx.x;
    g_bqkv[i] = (i < 1024) ? bq[i] : (i < 2048) ? bk[i - 1024] : bv[i - 2048];
}

__global__ __launch_bounds__(256) void embed_kernel(const int* __restrict__ x,
                                                    const float* __restrict__ emb) {
    int tok = blockIdx.x, s = tok % SS, id = x[tok];
    int d0 = threadIdx.x * 4;
    float4 ev = *(const float4*)(emb + (size_t)id * DD + d0);
    float o[4] = {ev.x, ev.y, ev.z, ev.w};
#pragma unroll
    for (int j = 0; j < 4; j++) {
        int d = d0 + j;
        float ang = (float)s * expf((float)(d & ~1) * (-9.210340371976184f / 1024.0f));
        o[j] = o[j] * 32.0f + ((d & 1) ? cosf(ang) : sinf(ang));
    }
    *(float4*)(g_h + (size_t)tok * DD + d0) = make_float4(o[0], o[1], o[2], o[3]);
}

// ===== mma.sync 3xTF32 GEMM: C[M,N] = [res+] A[M,K]@B + bias [relu]
#define KCH 16
#define ROWW 20
#define MATB (128*ROWW*4)
#define STGB (3*MATB)
#define TGSM (3*STGB)

__global__ __launch_bounds__(256, 2)
void tgemm_kernel(const float* __restrict__ A, const float* __restrict__ Bh,
                  const float* __restrict__ Bl, const float* __restrict__ bias,
                  const float* __restrict__ res, float* __restrict__ C,
                  int M, int N, int K, int relu) {
    extern __shared__ char smem[];
    unsigned sb = smem_u32(smem);
    int tid = threadIdx.x, wid = tid >> 5, lane = tid & 31;
    int grp = lane >> 2, qid = lane & 3;
    int bm = blockIdx.y * 128, bn = blockIdx.x * 128;
    int wm0 = (wid & 3) * 32, wn0 = (wid >> 2) * 64;

    float acc[2][8][4];
#pragma unroll
    for (int mt = 0; mt < 2; mt++)
#pragma unroll
        for (int nt = 0; nt < 8; nt++)
#pragma unroll
            for (int e = 0; e < 4; e++) acc[mt][nt][e] = 0.f;

    int nchunks = K / KCH;
    int r0 = tid >> 2, kc0 = (tid & 3) * 16;
    int r1 = (tid + 256) >> 2, kc1 = ((tid + 256) & 3) * 16;

#pragma unroll
    for (int c = 0; c < 2; c++) {
        int kb = c * KCH;
        unsigned st = sb + (c % 3) * STGB;
        CP16(st + r0 * 80 + kc0, A + (size_t)(bm + r0) * K + kb + kc0 / 4);
        CP16(st + r1 * 80 + kc1, A + (size_t)(bm + r1) * K + kb + kc1 / 4);
        CP16(st + MATB + r0 * 80 + kc0, Bh + (size_t)(bn + r0) * K + kb + kc0 / 4);
        CP16(st + MATB + r1 * 80 + kc1, Bh + (size_t)(bn + r1) * K + kb + kc1 / 4);
        CP16(st + 2 * MATB + r0 * 80 + kc0, Bl + (size_t)(bn + r0) * K + kb + kc0 / 4);
        CP16(st + 2 * MATB + r1 * 80 + kc1, Bl + (size_t)(bn + r1) * K + kb + kc1 / 4);
        asm volatile("cp.async.commit_group;");
    }

    for (int c = 0; c < nchunks; c++) {
        if (c + 2 < nchunks) asm volatile("cp.async.wait_group 1;");
        else                 asm volatile("cp.async.wait_group 0;");
        __syncthreads();
        const float* As  = (const float*)(smem + (c % 3) * STGB);
        const float* Bhs = As + 128 * ROWW;
        const float* Bls = Bhs + 128 * ROWW;
#pragma unroll
        for (int s8 = 0; s8 < 2; s8++) {
            int k8 = s8 * 8;
            unsigned Ah[2][4], Al[2][4];
#pragma unroll
            for (int mt = 0; mt < 2; mt++) {
                int ra = wm0 + mt * 16 + grp;
                float x0 = As[ra * ROWW + k8 + qid];
                float x1 = As[(ra + 8) * ROWW + k8 + qid];
                float x2 = As[ra * ROWW + k8 + qid + 4];
                float x3 = As[(ra + 8) * ROWW + k8 + qid + 4];
                float h0 = to_tf32f(x0), h1 = to_tf32f(x1), h2 = to_tf32f(x2), h3 = to_tf32f(x3);
                Ah[mt][0] = __float_as_uint(h0); Ah[mt][1] = __float_as_uint(h1);
                Ah[mt][2] = __float_as_uint(h2); Ah[mt][3] = __float_as_uint(h3);
                Al[mt][0] = __float_as_uint(to_tf32f(x0 - h0));
                Al[mt][1] = __float_as_uint(to_tf32f(x1 - h1));
                Al[mt][2] = __float_as_uint(to_tf32f(x2 - h2));
                Al[mt][3] = __float_as_uint(to_tf32f(x3 - h3));
            }
#pragma unroll
            for (int nt = 0; nt < 8; nt++) {
                int nr = wn0 + nt * 8 + grp;
                unsigned bh[2], bl[2];
                bh[0] = __float_as_uint(Bhs[nr * ROWW + k8 + qid]);
                bh[1] = __float_as_uint(Bhs[nr * ROWW + k8 + qid + 4]);
                bl[0] = __float_as_uint(Bls[nr * ROWW + k8 + qid]);
                bl[1] = __float_as_uint(Bls[nr * ROWW + k8 + qid + 4]);
#pragma unroll
                for (int mt = 0; mt < 2; mt++) {
                    mma8(acc[mt][nt], Ah[mt], bh);
                    mma8(acc[mt][nt], Ah[mt], bl);
                    mma8(acc[mt][nt], Al[mt], bh);
                }
            }
        }
        __syncthreads();
        if (c + 2 < nchunks) {
            int kb = (c + 2) * KCH;
            unsigned st = sb + ((c + 2) % 3) * STGB;
            CP16(st + r0 * 80 + kc0, A + (size_t)(bm + r0) * K + kb + kc0 / 4);
            CP16(st + r1 * 80 + kc1, A + (size_t)(bm + r1) * K + kb + kc1 / 4);
            CP16(st + MATB + r0 * 80 + kc0, Bh + (size_t)(bn + r0) * K + kb + kc0 / 4);
            CP16(st + MATB + r1 * 80 + kc1, Bh + (size_t)(bn + r1) * K + kb + kc1 / 4);
            CP16(st + 2 * MATB + r0 * 80 + kc0, Bl + (size_t)(bn + r0) * K + kb + kc0 / 4);
            CP16(st + 2 * MATB + r1 * 80 + kc1, Bl + (size_t)(bn + r1) * K + kb + kc1 / 4);
            asm volatile("cp.async.commit_group;");
        }
    }

#pragma unroll
    for (int mt = 0; mt < 2; mt++) {
#pragma unroll
        for (int nt = 0; nt < 8; nt++) {
            int row0 = bm + wm0 + mt * 16 + grp;
            int col = bn + wn0 + nt * 8 + 2 * qid;
            float2 v0 = make_float2(acc[mt][nt][0], acc[mt][nt][1]);
            float2 v1 = make_float2(acc[mt][nt][2], acc[mt][nt][3]);
            if (bias) {
                float2 bv = *(const float2*)(bias + col);
                v0.x += bv.x; v0.y += bv.y; v1.x += bv.x; v1.y += bv.y;
            }
            if (res) {
                float2 ra = *(const float2*)(res + (size_t)row0 * N + col);
                float2 rb = *(const float2*)(res + (size_t)(row0 + 8) * N + col);
                v0.x += ra.x; v0.y += ra.y; v1.x += rb.x; v1.y += rb.y;
            }
            if (relu) {
                v0.x = fmaxf(v0.x, 0.f); v0.y = fmaxf(v0.y, 0.f);
                v1.x = fmaxf(v1.x, 0.f); v1.y = fmaxf(v1.y, 0.f);
            }
            *(float2*)(C + (size_t)row0 * N + col) = v0;
            *(float2*)(C + (size_t)(row0 + 8) * N + col) = v1;
        }
    }
}

// ===== tensor-core attention scores: S = Q Kt / 8, lower-triangle 128x128 tiles ====
#define ASTR 68
#define SCSM (4*128*ASTR*4)     // Qh Ql Kh Kl

__global__ __launch_bounds__(256)
void attn_scores_mma_kernel() {
    int t = blockIdx.x;
    int qt = (int)((sqrtf(8.f * t + 1.f) - 1.f) * 0.5f);
    while ((qt + 1) * (qt + 2) / 2 <= t) qt++;
    while (qt * (qt + 1) / 2 > t) qt--;
    int kt = t - qt * (qt + 1) / 2;
    int bh = blockIdx.y;
    int b = bh >> 4, hh = bh & 15;

    extern __shared__ float sm[];
    float* QH = sm;
    float* QL = QH + 128 * ASTR;
    float* KH = QL + 128 * ASTR;
    float* KL = KH + 128 * ASTR;

    int tid = threadIdx.x, wid = tid >> 5, lane = tid & 31;
    int grp = lane >> 2, qid = lane & 3;
    int wm0 = (wid & 3) * 32, wn0 = (wid >> 2) * 64;

    const float* qb = g_qkv + ((size_t)(b * SS + qt * 128)) * QKVS + hh * HD;
    const float* kb = g_qkv + ((size_t)(b * SS + kt * 128)) * QKVS + 1024 + hh * HD;
    for (int i = tid; i < 128 * 16; i += 256) {
        int row = i >> 4, c4 = (i & 15) * 4;
        float4 v = *(const float4*)(qb + (size_t)row * QKVS + c4);
        float4 h = hi4(v);
        *(float4*)(QH + row * ASTR + c4) = h;
        *(float4*)(QL + row * ASTR + c4) = lo4(v, h);
        float4 w = *(const float4*)(kb + (size_t)row * QKVS + c4);
        float4 wh = hi4(w);
        *(float4*)(KH + row * ASTR + c4) = wh;
        *(float4*)(KL + row * ASTR + c4) = lo4(w, wh);
    }
    __syncthreads();

    float acc[2][8][4];
#pragma unroll
    for (int mt = 0; mt < 2; mt++)
#pragma unroll
        for (int nt = 0; nt < 8; nt++)
#pragma unroll
            for (int e = 0; e < 4; e++) acc[mt][nt][e] = 0.f;

#pragma unroll
    for (int s = 0; s < 8; s++) {
        int k8 = s * 8;
        unsigned Ah[2][4], Al[2][4];
#pragma unroll
        for (int mt = 0; mt < 2; mt++) {
            int ra = wm0 + mt * 16 + grp;
            Ah[mt][0] = __float_as_uint(QH[ra * ASTR + k8 + qid]);
            Ah[mt][1] = __float_as_uint(QH[(ra + 8) * ASTR + k8 + qid]);
            Ah[mt][2] = __float_as_uint(QH[ra * ASTR + k8 + qid + 4]);
            Ah[mt][3] = __float_as_uint(QH[(ra + 8) * ASTR + k8 + qid + 4]);
            Al[mt][0] = __float_as_uint(QL[ra * ASTR + k8 + qid]);
            Al[mt][1] = __float_as_uint(QL[(ra + 8) * ASTR + k8 + qid]);
            Al[mt][2] = __float_as_uint(QL[ra * ASTR + k8 + qid + 4]);
            Al[mt][3] = __float_as_uint(QL[(ra + 8) * ASTR + k8 + qid + 4]);
        }
#pragma unroll
        for (int nt = 0; nt < 8; nt++) {
            int nr = wn0 + nt * 8 + grp;
            unsigned bh2[2], bl2[2];
            bh2[0] = __float_as_uint(KH[nr * ASTR + k8 + qid]);
            bh2[1] = __float_as_uint(KH[nr * ASTR + k8 + qid + 4]);
            bl2[0] = __float_as_uint(KL[nr * ASTR + k8 + qid]);
            bl2[1] = __float_as_uint(KL[nr * ASTR + k8 + qid + 4]);
#pragma unroll
            for (int mt = 0; mt < 2; mt++) {
                mma8(acc[mt][nt], Ah[mt], bh2);
                mma8(acc[mt][nt], Ah[mt], bl2);
                mma8(acc[mt][nt], Al[mt], bh2);
            }
        }
    }

    bool diag = (kt == qt);
#pragma unroll
    for (int mt = 0; mt < 2; mt++) {
#pragma unroll
        for (int nt = 0; nt < 8; nt++) {
            int r0 = qt * 128 + wm0 + mt * 16 + grp;
            int c0 = kt * 128 + wn0 + nt * 8 + 2 * qid;
            float v0 = acc[mt][nt][0] * 0.125f, v1 = acc[mt][nt][1] * 0.125f;
            float v2 = acc[mt][nt][2] * 0.125f, v3 = acc[mt][nt][3] * 0.125f;
            if (diag) {
                if (c0 > r0)     v0 = -1e30f;
                if (c0 + 1 > r0) v1 = -1e30f;
                if (c0 > r0 + 8)     v2 = -1e30f;
                if (c0 + 1 > r0 + 8) v3 = -1e30f;
            }
            float* p0 = g_sc + ((size_t)bh * SS + r0) * SS + c0;
            *(float2*)p0 = make_float2(v0, v1);
            *(float2*)(p0 + 8 * SS) = make_float2(v2, v3);
        }
    }
}

// ===== prefix softmax: row q processes first L=(tile(q)+1)*128 cols =====
__global__ __launch_bounds__(256) void softmax_kernel() {
    int row = blockIdx.x;
    int qr = row & (SS - 1);
    int L = ((qr >> 7) + 1) << 7;
    float* sc = g_sc + (size_t)row * SS;
    int tid = threadIdx.x;
    bool valid = (tid * 4 < L);
    float4 v = valid ? *(float4*)&sc[tid * 4] : make_float4(-1e30f, -1e30f, -1e30f, -1e30f);
    __shared__ float red[8];
    __shared__ float stat;
    float m = fmaxf(fmaxf(v.x, v.y), fmaxf(v.z, v.w));
    for (int o = 16; o; o >>= 1) m = fmaxf(m, __shfl_down_sync(~0u, m, o));
    if ((tid & 31) == 0) red[tid >> 5] = m;
    __syncthreads();
    if (tid == 0) {
        float t = red[0];
        for (int i = 1; i < 8; i++) t = fmaxf(t, red[i]);
        stat = t;
    }
    __syncthreads();
    float mx = stat;
    float e0 = expf(v.x - mx), e1 = expf(v.y - mx), e2 = expf(v.z - mx), e3 = expf(v.w - mx);
    float s = e0 + e1 + e2 + e3;
    for (int o = 16; o; o >>= 1) s += __shfl_down_sync(~0u, s, o);
    __syncthreads();
    if ((tid & 31) == 0) red[tid >> 5] = s;
    __syncthreads();
    if (tid == 0) {
        float t = 0.f;
        for (int i = 0; i < 8; i++) t += red[i];
        stat = t;
    }
    __syncthreads();
    float inv = 1.0f / stat;
    if (valid) *(float4*)&sc[tid * 4] = make_float4(e0 * inv, e1 * inv, e2 * inv, e3 * inv);
}

// ===== tensor-core AV: O = P @ V, kv chunks of 64 =====
#define AVSM ((2*128 + 2*64)*ASTR*4)

__global__ __launch_bounds__(256)
void attn_av_mma_kernel() {
    int qt = blockIdx.x, bh = blockIdx.y;
    int b = bh >> 4, hh = bh & 15;

    extern __shared__ float sm[];
    float* PH = sm;
    float* PL = PH + 128 * ASTR;
    float* VH = PL + 128 * ASTR;
    float* VL = VH + 64 * ASTR;

    int tid = threadIdx.x, wid = tid >> 5, lane = tid & 31;
    int grp = lane >> 2, qid = lane & 3;
    int wm0 = (wid & 3) * 32, wn0 = (wid >> 2) * 32;

    float acc[2][4][4];
#pragma unroll
    for (int mt = 0; mt < 2; mt++)
#pragma unroll
        for (int nt = 0; nt < 4; nt++)
#pragma unroll
            for (int e = 0; e < 4; e++) acc[mt][nt][e] = 0.f;

    int nchunks = (qt + 1) * 2;
    for (int kc = 0; kc < nchunks; kc++) {
        // stage P chunk [128 x 64] split
        const float* pb = g_sc + ((size_t)bh * SS + qt * 128) * SS + kc * 64;
        for (int i = tid; i < 128 * 16; i += 256) {
            int row = i >> 4, c4 = (i & 15) * 4;
            float4 v = *(const float4*)(pb + (size_t)row * SS + c4);
            float4 h = hi4(v);
            *(float4*)(PH + row * ASTR + c4) = h;
            *(float4*)(PL + row * ASTR + c4) = lo4(v, h);
        }
        // stage V chunk transposed: VH[dim][tok]
        const float* vb = g_qkv + ((size_t)(b * SS + kc * 64)) * QKVS + 2048 + hh * HD;
        for (int i = tid; i < 64 * 16; i += 256) {
            int tok = i >> 4, d4 = (i & 15) * 4;
            float4 v = *(const float4*)(vb + (size_t)tok * QKVS + d4);
            float4 h = hi4(v);
            float4 l = lo4(v, h);
            VH[(d4 + 0) * ASTR + tok] = h.x; VL[(d4 + 0) * ASTR + tok] = l.x;
            VH[(d4 + 1) * ASTR + tok] = h.y; VL[(d4 + 1) * ASTR + tok] = l.y;
            VH[(d4 + 2) * ASTR + tok] = h.z; VL[(d4 + 2) * ASTR + tok] = l.z;
            VH[(d4 + 3) * ASTR + tok] = h.w; VL[(d4 + 3) * ASTR + tok] = l.w;
        }
        __syncthreads();
#pragma unroll
        for (int s = 0; s < 8; s++) {
            int k8 = s * 8;
            unsigned Ah[2][4], Al[2][4];
#pragma unroll
            for (int mt = 0; mt < 2; mt++) {
                int ra = wm0 + mt * 16 + grp;
                Ah[mt][0] = __float_as_uint(PH[ra * ASTR + k8 + qid]);
                Ah[mt][1] = __float_as_uint(PH[(ra + 8) * ASTR + k8 + qid]);
                Ah[mt][2] = __float_as_uint(PH[ra * ASTR + k8 + qid + 4]);
                Ah[mt][3] = __float_as_uint(PH[(ra + 8) * ASTR + k8 + qid + 4]);
                Al[mt][0] = __float_as_uint(PL[ra * ASTR + k8 + qid]);
                Al[mt][1] = __float_as_uint(PL[(ra + 8) * ASTR + k8 + qid]);
                Al[mt][2] = __float_as_uint(PL[ra * ASTR + k8 + qid + 4]);
                Al[mt][3] = __float_as_uint(PL[(ra + 8) * ASTR + k8 + qid + 4]);
            }
#pragma unroll
            for (int nt = 0; nt < 4; nt++) {
                int nr = wn0 + nt * 8 + grp;
                unsigned bh2[2], bl2[2];
                bh2[0] = __float_as_uint(VH[nr * ASTR + k8 + qid]);
                bh2[1] = __float_as_uint(VH[nr * ASTR + k8 + qid + 4]);
                bl2[0] = __float_as_uint(VL[nr * ASTR + k8 + qid]);
                bl2[1] = __float_as_uint(VL[nr * ASTR + k8 + qid + 4]);
#pragma unroll
                for (int mt = 0; mt < 2; mt++) {
                    mma8(acc[mt][nt], Ah[mt], bh2);
                    mma8(acc[mt][nt], Ah[mt], bl2);
                    mma8(acc[mt][nt], Al[mt], bh2);
                }
            }
        }
        __syncthreads();
    }

#pragma unroll
    for (int mt = 0; mt < 2; mt++) {
#pragma unroll
        for (int nt = 0; nt < 4; nt++) {
            int r0 = qt * 128 + wm0 + mt * 16 + grp;
            int c0 = hh * HD + wn0 + nt * 8 + 2 * qid;
            float* p0 = g_a + ((size_t)(b * SS) + r0) * DD + c0;
            *(float2*)p0 = make_float2(acc[mt][nt][0], acc[mt][nt][1]);
            *(float2*)(p0 + 8 * DD) = make_float2(acc[mt][nt][2], acc[mt][nt][3]);
        }
    }
}

// ===== SIMT SGEMM (router GEMM1 only, N=128) =====
__global__ __launch_bounds__(256) void sgemm_kernel(const float* __restrict__ A,
                                                    const float* __restrict__ B,
                                                    const float* __restrict__ bias,
                                                    float* __restrict__ C,
                                                    int M, int N, int K) {
    __shared__ float Ast[16][128];
    __shared__ float Bs[16][64];
    int tid = threadIdx.x;
    int bm = blockIdx.y * 128, bn = blockIdx.x * 64;
    int tx = tid & 15, ty = tid >> 4;
    int m0 = ty * 8, n0 = tx * 4;
    float acc[8][4];
#pragma unroll
    for (int i = 0; i < 8; i++)
#pragma unroll
        for (int j = 0; j < 4; j++) acc[i][j] = 0.f;
    int arow = tid >> 2, ak4 = (tid & 3) * 4, bk = tid >> 4, bc4 = (tid & 15) * 4;
    for (int kb = 0; kb < K; kb += 16) {
#pragma unroll
        for (int p = 0; p < 2; p++) {
            int r = arow + p * 64;
            float4 av = *(const float4*)(A + (size_t)(bm + r) * K + kb + ak4);
            Ast[ak4+0][r] = av.x; Ast[ak4+1][r] = av.y; Ast[ak4+2][r] = av.z; Ast[ak4+3][r] = av.w;
        }
        *(float4*)&Bs[bk][bc4] = *(const float4*)(B + (size_t)(kb + bk) * N + bn + bc4);
        __syncthreads();
#pragma unroll
        for (int k = 0; k < 16; k++) {
            float4 a0 = *(float4*)&Ast[k][m0];
            float4 a1 = *(float4*)&Ast[k][m0 + 4];
            float4 bv = *(float4*)&Bs[k][n0];
            float am[8] = {a0.x,a0.y,a0.z,a0.w,a1.x,a1.y,a1.z,a1.w};
            float bb[4] = {bv.x,bv.y,bv.z,bv.w};
#pragma unroll
            for (int i = 0; i < 8; i++)
#pragma unroll
                for (int j = 0; j < 4; j++) acc[i][j] += am[i] * bb[j];
        }
        __syncthreads();
    }
#pragma unroll
    for (int i = 0; i < 8; i++)
#pragma unroll
        for (int j = 0; j < 4; j++) {
            float v = acc[i][j] + bias[bn + n0 + j];
            C[(size_t)(bm + m0 + i) * N + bn + n0 + j] = fmaxf(v, 0.f);
        }
}

__global__ __launch_bounds__(256) void ln_kernel(const float* __restrict__ in,
                                                 const float* __restrict__ g,
                                                 const float* __restrict__ bsh,
                                                 float* __restrict__ out) {
    size_t row = blockIdx.x;
    const float* x = in + row * DD;
    int tid = threadIdx.x;
    float4 v = *(const float4*)&x[tid * 4];
    __shared__ float red[8];
    __shared__ float stat;
    float s = v.x + v.y + v.z + v.w;
    for (int o = 16; o; o >>= 1) s += __shfl_down_sync(~0u, s, o);
    if ((tid & 31) == 0) red[tid >> 5] = s;
    __syncthreads();
    if (tid == 0) {
        float t = 0.f;
        for (int i = 0; i < 8; i++) t += red[i];
        stat = t * (1.0f / DD);
    }
    __syncthreads();
    float mu = stat;
    float dx = v.x - mu, dy = v.y - mu, dz = v.z - mu, dw = v.w - mu;
    float ss = dx * dx + dy * dy + dz * dz + dw * dw;
    for (int o = 16; o; o >>= 1) ss += __shfl_down_sync(~0u, ss, o);
    __syncthreads();
    if ((tid & 31) == 0) red[tid >> 5] = ss;
    __syncthreads();
    if (tid == 0) {
        float t = 0.f;
        for (int i = 0; i < 8; i++) t += red[i];
        stat = rsqrtf(t * (1.0f / DD) + 1e-5f);
    }
    __syncthreads();
    float rs = stat;
    float4 gg = *(const float4*)&g[tid * 4];
    float4 bb = *(const float4*)&bsh[tid * 4];
    *(float4*)&out[row * DD + tid * 4] =
        make_float4(dx * rs * gg.x + bb.x, dy * rs * gg.y + bb.y,
                    dz * rs * gg.z + bb.z, dw * rs * gg.w + bb.w);
}

__global__ __launch_bounds__(256) void router2_kernel(const float* __restrict__ rw2,
                                                      const float* __restrict__ rb2) {
    int w = (blockIdx.x * blockDim.x + threadIdx.x) >> 5;
    int lane = threadIdx.x & 31;
    if (w >= MM) return;
    const float* z = g_zr + (size_t)w * RH;
    float s0 = 0.f, s1 = 0.f, s2 = 0.f;
#pragma unroll
    for (int u = 0; u < 4; u++) {
        int j = lane + 32 * u;
        float zv = z[j];
        s0 += zv * rw2[j * 3 + 0];
        s1 += zv * rw2[j * 3 + 1];
        s2 += zv * rw2[j * 3 + 2];
    }
    for (int o = 16; o; o >>= 1) {
        s0 += __shfl_down_sync(~0u, s0, o);
        s1 += __shfl_down_sync(~0u, s1, o);
        s2 += __shfl_down_sync(~0u, s2, o);
    }
    if (lane == 0) {
        s0 += rb2[0]; s1 += rb2[1]; s2 += rb2[2];
        int a = 0; float best = s0;
        if (s1 > best) { best = s1; a = 1; }
        if (s2 > best) { best = s2; a = 2; }
        g_skip[w] = (a == 0);
        atomicAdd(&g_cnt[a], 1);
    }
}

__global__ __launch_bounds__(256) void merge_kernel() {
    int tok = blockIdx.x;
    if (g_skip[tok]) return;
    ((float4*)g_h)[(size_t)tok * 256 + threadIdx.x] =
        ((float4*)g_ht)[(size_t)tok * 256 + threadIdx.x];
}

__global__ void scalars_kernel(float* out) {
    float fs = (float)g_cnt[0], ff = (float)g_cnt[1], fr = (float)g_cnt[2];
    out[(size_t)MM * VOC + 0] = (ff + fr) / (float)MM;
    out[(size_t)MM * VOC + 1] = fs / (float)(MM * NL);
    out[(size_t)MM * VOC + 2] = ff / (float)(MM * NL);
    out[(size_t)MM * VOC + 3] = fr / (float)(MM * NL);
}

extern "C" void kernel_launch(void* const* d_in, const int* in_sizes, int n_in,
                              void* d_out, int out_size) {
    const int*   x    = (const int*)d_in[0];
    const float* emb  = (const float*)d_in[1];
    const float* Wq   = (const float*)d_in[2];
    const float* bq   = (const float*)d_in[3];
    const float* Wk   = (const float*)d_in[4];
    const float* bk   = (const float*)d_in[5];
    const float* Wv   = (const float*)d_in[6];
    const float* bv   = (const float*)d_in[7];
    const float* Wo   = (const float*)d_in[8];
    const float* bo   = (const float*)d_in[9];
    const float* ln1g = (const float*)d_in[10];
    const float* ln1b = (const float*)d_in[11];
    const float* Wf1  = (const float*)d_in[12];
    const float* bf1  = (const float*)d_in[13];
    const float* Wf2  = (const float*)d_in[14];
    const float* bf2  = (const float*)d_in[15];
    const float* ln2g = (const float*)d_in[16];
    const float* ln2b = (const float*)d_in[17];
    const float* rW1  = (const float*)d_in[18];
    const float* rb1  = (const float*)d_in[19];
    const float* rW2  = (const float*)d_in[20];
    const float* rb2  = (const float*)d_in[21];
    const float* Wout = (const float*)d_in[22];
    const float* bout = (const float*)d_in[23];
    float* out = (float*)d_out;

    cudaFuncSetAttribute(tgemm_kernel, cudaFuncAttributeMaxDynamicSharedMemorySize, TGSM);
    cudaFuncSetAttribute(attn_scores_mma_kernel, cudaFuncAttributeMaxDynamicSharedMemorySize, SCSM);
    cudaFuncSetAttribute(attn_av_mma_kernel, cudaFuncAttributeMaxDynamicSharedMemorySize, AVSM);

    float *h, *h1, *t, *qkv, *a, *ht, *f1, *zr;
    float *wqh, *wql, *woh, *wol, *w1h, *w1l, *w2h, *w2l, *wvh, *wvl, *bqkv;
    cudaGetSymbolAddress((void**)&h, g_h);
    cudaGetSymbolAddress((void**)&h1, g_h1);
    cudaGetSymbolAddress((void**)&t, g_t);
    cudaGetSymbolAddress((void**)&qkv, g_qkv);
    cudaGetSymbolAddress((void**)&a, g_a);
    cudaGetSymbolAddress((void**)&ht, g_ht);
    cudaGetSymbolAddress((void**)&f1, g_f1);
    cudaGetSymbolAddress((void**)&zr, g_zr);
    cudaGetSymbolAddress((void**)&wqh, g_wqkv_h);
    cudaGetSymbolAddress((void**)&wql, g_wqkv_l);
    cudaGetSymbolAddress((void**)&woh, g_wo_h);
    cudaGetSymbolAddress((void**)&wol, g_wo_l);
    cudaGetSymbolAddress((void**)&w1h, g_wf1_h);
    cudaGetSymbolAddress((void**)&w1l, g_wf1_l);
    cudaGetSymbolAddress((void**)&w2h, g_wf2_h);
    cudaGetSymbolAddress((void**)&w2l, g_wf2_l);
    cudaGetSymbolAddress((void**)&wvh, g_wout_h);
    cudaGetSymbolAddress((void**)&wvl, g_wout_l);
    cudaGetSymbolAddress((void**)&bqkv, g_bqkv);

    wtrans_kernel<<<dim3(DD/32, DD/32), 256>>>(Wq, wqh, wql, DD, DD);
    wtrans_kernel<<<dim3(DD/32, DD/32), 256>>>(Wk, wqh + (size_t)1024*DD, wql + (size_t)1024*DD, DD, DD);
    wtrans_kernel<<<dim3(DD/32, DD/32), 256>>>(Wv, wqh + (size_t)2048*DD, wql + (size_t)2048*DD, DD, DD);
    wtrans_kernel<<<dim3(DD/32, DD/32), 256>>>(Wo, woh, wol, DD, DD);
    wtrans_kernel<<<dim3(DFF/32, DD/32), 256>>>(Wf1, w1h, w1l, DD, DFF);
    wtrans_kernel<<<dim3(DD/32, DFF/32), 256>>>(Wf2, w2h, w2l, DFF, DD);
    wtrans_kernel<<<dim3(VOC/32, DD/32), 256>>>(Wout, wvh, wvl, DD, VOC);
    bcat_kernel<<<QKVS/256, 256>>>(bq, bk, bv);

    zero_cnt_kernel<<<1, 32>>>();
    embed_kernel<<<MM, 256>>>(x, emb);

    for (int l = 0; l < NL; l++) {
        sgemm_kernel<<<dim3(RH/64, MM/128), 256>>>(h, rW1 + (size_t)l*DD*RH, rb1 + l*RH, zr, MM, RH, DD);
        router2_kernel<<<MM/8, 256>>>(rW2 + (size_t)l*RH*3, rb2 + l*3);
        tgemm_kernel<<<dim3(QKVS/128, MM/128), 256, TGSM>>>(h, wqh, wql, bqkv, nullptr, qkv, MM, QKVS, DD, 0);
        attn_scores_mma_kernel<<<dim3(36, BHT), 256, SCSM>>>();
        softmax_kernel<<<BHT*SS, 256>>>();
        attn_av_mma_kernel<<<dim3(SS/128, BHT), 256, AVSM>>>();
        tgemm_kernel<<<dim3(DD/128, MM/128), 256, TGSM>>>(a, woh, wol, bo, h, t, MM, DD, DD, 0);
        ln_kernel<<<MM, 256>>>(t, ln1g, ln1b, h1);
        tgemm_kernel<<<dim3(DFF/128, MM/128), 256, TGSM>>>(h1, w1h, w1l, bf1, nullptr, f1, MM, DFF, DD, 1);
        tgemm_kernel<<<dim3(DD/128, MM/128), 256, TGSM>>>(f1, w2h, w2l, bf2, h1, t, MM, DD, DFF, 0);
        ln_kernel<<<MM, 256>>>(t, ln2g, ln2b, ht);
        merge_kernel<<<MM, 256>>>();
    }

    tgemm_kernel<<<dim3(VOC/128, MM/128), 256, TGSM>>>(h, wvh, wvl, bout, nullptr, out, MM, VOC, DD, 0);
    scalars_kernel<<<1, 1>>>(out);
}

// round 7
// speedup vs baseline: 3.6701x; 1.0399x over previous
#include <cuda_runtime.h>
#include <math.h>
#include <stdint.h>

#define BB 2
#define SS 1024
#define DD 1024
#define NH 16
#define HD 64
#define NL 12
#define DFF 4096
#define RH 128
#define VOC 32000
#define MM (BB*SS)
#define BHT (BB*NH)
#define QKVS 3072

// ---- static scratch ----
__device__ float g_h [MM*DD];
__device__ float g_h1[MM*DD];
__device__ float g_t [MM*DD];
__device__ float g_t2[MM*DD];
__device__ float g_qkv[MM*QKVS];
__device__ float g_a [MM*DD];
__device__ float g_f1[MM*DFF];
__device__ float g_zr[MM*RH];
__device__ float g_sc[(size_t)BHT*SS*SS];
__device__ unsigned char g_skip[MM];
__device__ int g_cnt[3];
__device__ float g_wqkv_h[(size_t)QKVS*DD], g_wqkv_l[(size_t)QKVS*DD];
__device__ float g_wo_h[(size_t)DD*DD],     g_wo_l[(size_t)DD*DD];
__device__ float g_wf1_h[(size_t)DFF*DD],   g_wf1_l[(size_t)DFF*DD];
__device__ float g_wf2_h[(size_t)DD*DFF],   g_wf2_l[(size_t)DD*DFF];
__device__ float g_wout_h[(size_t)VOC*DD],  g_wout_l[(size_t)VOC*DD];
__device__ float g_bqkv[QKVS];

static __device__ __forceinline__ unsigned smem_u32(const void* p) {
    unsigned r;
    asm("{ .reg .u64 t; cvta.to.shared.u64 t, %1; cvt.u32.u64 %0, t; }" : "=r"(r) : "l"(p));
    return r;
}
static __device__ __forceinline__ float to_tf32f(float x) {
    float r; asm("cvt.rna.tf32.f32 %0, %1;" : "=f"(r) : "f"(x)); return r;
}
static __device__ __forceinline__ void mma8(float* c, const unsigned* a, const unsigned* b) {
    asm volatile(
        "mma.sync.aligned.m16n8k8.row.col.f32.tf32.tf32.f32 "
        "{%0,%1,%2,%3}, {%4,%5,%6,%7}, {%8,%9}, {%0,%1,%2,%3};"
        : "+f"(c[0]), "+f"(c[1]), "+f"(c[2]), "+f"(c[3])
        : "r"(a[0]), "r"(a[1]), "r"(a[2]), "r"(a[3]), "r"(b[0]), "r"(b[1]));
}
static __device__ __forceinline__ float4 hi4(float4 v) {
    return make_float4(to_tf32f(v.x), to_tf32f(v.y), to_tf32f(v.z), to_tf32f(v.w));
}
static __device__ __forceinline__ float4 lo4(float4 v, float4 h) {
    return make_float4(to_tf32f(v.x - h.x), to_tf32f(v.y - h.y),
                       to_tf32f(v.z - h.z), to_tf32f(v.w - h.w));
}
#define CP16(dst, src) \
    asm volatile("cp.async.cg.shared.global [%0], [%1], 16;" :: "r"(dst), "l"(src))

__global__ void zero_cnt_kernel() { if (threadIdx.x < 3) g_cnt[threadIdx.x] = 0; }

// W[K][N] -> Th/Tl [N][K] with tf32 hi/lo split
__global__ __launch_bounds__(256) void wtrans_kernel(const float* __restrict__ W,
                                                     float* __restrict__ Th,
                                                     float* __restrict__ Tl, int K, int N) {
    __shared__ float tile[32][33];
    int n0 = blockIdx.x * 32, k0 = blockIdx.y * 32;
    int tx = threadIdx.x & 31, ty = threadIdx.x >> 5;
    for (int i = ty; i < 32; i += 8) tile[i][tx] = W[(size_t)(k0 + i) * N + n0 + tx];
    __syncthreads();
    for (int i = ty; i < 32; i += 8) {
        float v = tile[tx][i];
        float hv = to_tf32f(v);
        float lv = to_tf32f(v - hv);
        size_t o = (size_t)(n0 + i) * K + k0 + tx;
        Th[o] = hv; Tl[o] = lv;
    }
}

__global__ void bcat_kernel(const float* __restrict__ bq, const float* __restrict__ bk,
                            const float* __restrict__ bv) {
    int i = blockIdx.x * 256 + threadIdx.x;
    g_bqkv[i] = (i < 1024) ? bq[i] : (i < 2048) ? bk[i - 1024] : bv[i - 2048];
}

__global__ __launch_bounds__(256) void embed_kernel(const int* __restrict__ x,
                                                    const float* __restrict__ emb) {
    int tok = blockIdx.x, s = tok % SS, id = x[tok];
    int d0 = threadIdx.x * 4;
    float4 ev = *(const float4*)(emb + (size_t)id * DD + d0);
    float o[4] = {ev.x, ev.y, ev.z, ev.w};
#pragma unroll
    for (int j = 0; j < 4; j++) {
        int d = d0 + j;
        float ang = (float)s * expf((float)(d & ~1) * (-9.210340371976184f / 1024.0f));
        o[j] = o[j] * 32.0f + ((d & 1) ? cosf(ang) : sinf(ang));
    }
    *(float4*)(g_h + (size_t)tok * DD + d0) = make_float4(o[0], o[1], o[2], o[3]);
}

// ===== mma.sync 3xTF32 GEMM with optional split-K (gridDim.z=2) =====
// C[M,N] = A[M,Ksub]@B + bias [relu]; split z writes to C0/C1 partials.
#define KCH 16
#define ROWW 20
#define MATB (128*ROWW*4)
#define STGB (3*MATB)
#define TGSM (3*STGB)

__global__ __launch_bounds__(256, 2)
void tgemm_kernel(const float* __restrict__ A, const float* __restrict__ Bh,
                  const float* __restrict__ Bl, const float* __restrict__ bias,
                  float* __restrict__ C0, float* __restrict__ C1,
                  int M, int N, int Ksub, int ldk, int relu) {
    extern __shared__ char smem[];
    unsigned sb = smem_u32(smem);
    int z = blockIdx.z;
    A  += (size_t)z * Ksub;
    Bh += (size_t)z * Ksub;
    Bl += (size_t)z * Ksub;
    float* C = z ? C1 : C0;
    int tid = threadIdx.x, wid = tid >> 5, lane = tid & 31;
    int grp = lane >> 2, qid = lane & 3;
    int bm = blockIdx.y * 128, bn = blockIdx.x * 128;
    int wm0 = (wid & 3) * 32, wn0 = (wid >> 2) * 64;

    float acc[2][8][4];
#pragma unroll
    for (int mt = 0; mt < 2; mt++)
#pragma unroll
        for (int nt = 0; nt < 8; nt++)
#pragma unroll
            for (int e = 0; e < 4; e++) acc[mt][nt][e] = 0.f;

    int nchunks = Ksub / KCH;
    int r0 = tid >> 2, kc0 = (tid & 3) * 16;
    int r1 = (tid + 256) >> 2, kc1 = ((tid + 256) & 3) * 16;

#pragma unroll
    for (int c = 0; c < 2; c++) {
        int kb = c * KCH;
        unsigned st = sb + (c % 3) * STGB;
        CP16(st + r0 * 80 + kc0, A + (size_t)(bm + r0) * ldk + kb + kc0 / 4);
        CP16(st + r1 * 80 + kc1, A + (size_t)(bm + r1) * ldk + kb + kc1 / 4);
        CP16(st + MATB + r0 * 80 + kc0, Bh + (size_t)(bn + r0) * ldk + kb + kc0 / 4);
        CP16(st + MATB + r1 * 80 + kc1, Bh + (size_t)(bn + r1) * ldk + kb + kc1 / 4);
        CP16(st + 2 * MATB + r0 * 80 + kc0, Bl + (size_t)(bn + r0) * ldk + kb + kc0 / 4);
        CP16(st + 2 * MATB + r1 * 80 + kc1, Bl + (size_t)(bn + r1) * ldk + kb + kc1 / 4);
        asm volatile("cp.async.commit_group;");
    }

    for (int c = 0; c < nchunks; c++) {
        if (c + 2 < nchunks) asm volatile("cp.async.wait_group 1;");
        else                 asm volatile("cp.async.wait_group 0;");
        __syncthreads();
        const float* As  = (const float*)(smem + (c % 3) * STGB);
        const float* Bhs = As + 128 * ROWW;
        const float* Bls = Bhs + 128 * ROWW;
#pragma unroll
        for (int s8 = 0; s8 < 2; s8++) {
            int k8 = s8 * 8;
            unsigned Ah[2][4], Al[2][4];
#pragma unroll
            for (int mt = 0; mt < 2; mt++) {
                int ra = wm0 + mt * 16 + grp;
                float x0 = As[ra * ROWW + k8 + qid];
                float x1 = As[(ra + 8) * ROWW + k8 + qid];
                float x2 = As[ra * ROWW + k8 + qid + 4];
                float x3 = As[(ra + 8) * ROWW + k8 + qid + 4];
                float h0 = to_tf32f(x0), h1 = to_tf32f(x1), h2 = to_tf32f(x2), h3 = to_tf32f(x3);
                Ah[mt][0] = __float_as_uint(h0); Ah[mt][1] = __float_as_uint(h1);
                Ah[mt][2] = __float_as_uint(h2); Ah[mt][3] = __float_as_uint(h3);
                Al[mt][0] = __float_as_uint(to_tf32f(x0 - h0));
                Al[mt][1] = __float_as_uint(to_tf32f(x1 - h1));
                Al[mt][2] = __float_as_uint(to_tf32f(x2 - h2));
                Al[mt][3] = __float_as_uint(to_tf32f(x3 - h3));
            }
#pragma unroll
            for (int nt = 0; nt < 8; nt++) {
                int nr = wn0 + nt * 8 + grp;
                unsigned bh[2], bl[2];
                bh[0] = __float_as_uint(Bhs[nr * ROWW + k8 + qid]);
                bh[1] = __float_as_uint(Bhs[nr * ROWW + k8 + qid + 4]);
                bl[0] = __float_as_uint(Bls[nr * ROWW + k8 + qid]);
                bl[1] = __float_as_uint(Bls[nr * ROWW + k8 + qid + 4]);
#pragma unroll
                for (int mt = 0; mt < 2; mt++) {
                    mma8(acc[mt][nt], Ah[mt], bh);
                    mma8(acc[mt][nt], Ah[mt], bl);
                    mma8(acc[mt][nt], Al[mt], bh);
                }
            }
        }
        __syncthreads();
        if (c + 2 < nchunks) {
            int kb = (c + 2) * KCH;
            unsigned st = sb + ((c + 2) % 3) * STGB;
            CP16(st + r0 * 80 + kc0, A + (size_t)(bm + r0) * ldk + kb + kc0 / 4);
            CP16(st + r1 * 80 + kc1, A + (size_t)(bm + r1) * ldk + kb + kc1 / 4);
            CP16(st + MATB + r0 * 80 + kc0, Bh + (size_t)(bn + r0) * ldk + kb + kc0 / 4);
            CP16(st + MATB + r1 * 80 + kc1, Bh + (size_t)(bn + r1) * ldk + kb + kc1 / 4);
            CP16(st + 2 * MATB + r0 * 80 + kc0, Bl + (size_t)(bn + r0) * ldk + kb + kc0 / 4);
            CP16(st + 2 * MATB + r1 * 80 + kc1, Bl + (size_t)(bn + r1) * ldk + kb + kc1 / 4);
            asm volatile("cp.async.commit_group;");
        }
    }

#pragma unroll
    for (int mt = 0; mt < 2; mt++) {
#pragma unroll
        for (int nt = 0; nt < 8; nt++) {
            int row0 = bm + wm0 + mt * 16 + grp;
            int col = bn + wn0 + nt * 8 + 2 * qid;
            float2 v0 = make_float2(acc[mt][nt][0], acc[mt][nt][1]);
            float2 v1 = make_float2(acc[mt][nt][2], acc[mt][nt][3]);
            if (bias) {
                float2 bv = *(const float2*)(bias + col);
                v0.x += bv.x; v0.y += bv.y; v1.x += bv.x; v1.y += bv.y;
            }
            if (relu) {
                v0.x = fmaxf(v0.x, 0.f); v0.y = fmaxf(v0.y, 0.f);
                v1.x = fmaxf(v1.x, 0.f); v1.y = fmaxf(v1.y, 0.f);
            }
            *(float2*)(C + (size_t)row0 * N + col) = v0;
            *(float2*)(C + (size_t)(row0 + 8) * N + col) = v1;
        }
    }
}

// ===== tensor-core attention scores: S = Q Kt / 8, lower-triangle 128x128 tiles ====
#define ASTR 68
#define SCSM (4*128*ASTR*4)

__global__ __launch_bounds__(256)
void attn_scores_mma_kernel() {
    int t = blockIdx.x;
    int qt = (int)((sqrtf(8.f * t + 1.f) - 1.f) * 0.5f);
    while ((qt + 1) * (qt + 2) / 2 <= t) qt++;
    while (qt * (qt + 1) / 2 > t) qt--;
    int kt = t - qt * (qt + 1) / 2;
    int bh = blockIdx.y;
    int b = bh >> 4, hh = bh & 15;

    extern __shared__ float sm[];
    float* QH = sm;
    float* QL = QH + 128 * ASTR;
    float* KH = QL + 128 * ASTR;
    float* KL = KH + 128 * ASTR;

    int tid = threadIdx.x, wid = tid >> 5, lane = tid & 31;
    int grp = lane >> 2, qid = lane & 3;
    int wm0 = (wid & 3) * 32, wn0 = (wid >> 2) * 64;

    const float* qb = g_qkv + ((size_t)(b * SS + qt * 128)) * QKVS + hh * HD;
    const float* kb = g_qkv + ((size_t)(b * SS + kt * 128)) * QKVS + 1024 + hh * HD;
    for (int i = tid; i < 128 * 16; i += 256) {
        int row = i >> 4, c4 = (i & 15) * 4;
        float4 v = *(const float4*)(qb + (size_t)row * QKVS + c4);
        float4 h = hi4(v);
        *(float4*)(QH + row * ASTR + c4) = h;
        *(float4*)(QL + row * ASTR + c4) = lo4(v, h);
        float4 w = *(const float4*)(kb + (size_t)row * QKVS + c4);
        float4 wh = hi4(w);
        *(float4*)(KH + row * ASTR + c4) = wh;
        *(float4*)(KL + row * ASTR + c4) = lo4(w, wh);
    }
    __syncthreads();

    float acc[2][8][4];
#pragma unroll
    for (int mt = 0; mt < 2; mt++)
#pragma unroll
        for (int nt = 0; nt < 8; nt++)
#pragma unroll
            for (int e = 0; e < 4; e++) acc[mt][nt][e] = 0.f;

#pragma unroll
    for (int s = 0; s < 8; s++) {
        int k8 = s * 8;
        unsigned Ah[2][4], Al[2][4];
#pragma unroll
        for (int mt = 0; mt < 2; mt++) {
            int ra = wm0 + mt * 16 + grp;
            Ah[mt][0] = __float_as_uint(QH[ra * ASTR + k8 + qid]);
            Ah[mt][1] = __float_as_uint(QH[(ra + 8) * ASTR + k8 + qid]);
            Ah[mt][2] = __float_as_uint(QH[ra * ASTR + k8 + qid + 4]);
            Ah[mt][3] = __float_as_uint(QH[(ra + 8) * ASTR + k8 + qid + 4]);
            Al[mt][0] = __float_as_uint(QL[ra * ASTR + k8 + qid]);
            Al[mt][1] = __float_as_uint(QL[(ra + 8) * ASTR + k8 + qid]);
            Al[mt][2] = __float_as_uint(QL[ra * ASTR + k8 + qid + 4]);
            Al[mt][3] = __float_as_uint(QL[(ra + 8) * ASTR + k8 + qid + 4]);
        }
#pragma unroll
        for (int nt = 0; nt < 8; nt++) {
            int nr = wn0 + nt * 8 + grp;
            unsigned bh2[2], bl2[2];
            bh2[0] = __float_as_uint(KH[nr * ASTR + k8 + qid]);
            bh2[1] = __float_as_uint(KH[nr * ASTR + k8 + qid + 4]);
            bl2[0] = __float_as_uint(KL[nr * ASTR + k8 + qid]);
            bl2[1] = __float_as_uint(KL[nr * ASTR + k8 + qid + 4]);
#pragma unroll
            for (int mt = 0; mt < 2; mt++) {
                mma8(acc[mt][nt], Ah[mt], bh2);
                mma8(acc[mt][nt], Ah[mt], bl2);
                mma8(acc[mt][nt], Al[mt], bh2);
            }
        }
    }

    bool diag = (kt == qt);
#pragma unroll
    for (int mt = 0; mt < 2; mt++) {
#pragma unroll
        for (int nt = 0; nt < 8; nt++) {
            int r0 = qt * 128 + wm0 + mt * 16 + grp;
            int c0 = kt * 128 + wn0 + nt * 8 + 2 * qid;
            float v0 = acc[mt][nt][0] * 0.125f, v1 = acc[mt][nt][1] * 0.125f;
            float v2 = acc[mt][nt][2] * 0.125f, v3 = acc[mt][nt][3] * 0.125f;
            if (diag) {
                if (c0 > r0)     v0 = -1e30f;
                if (c0 + 1 > r0) v1 = -1e30f;
                if (c0 > r0 + 8)     v2 = -1e30f;
                if (c0 + 1 > r0 + 8) v3 = -1e30f;
            }
            float* p0 = g_sc + ((size_t)bh * SS + r0) * SS + c0;
            *(float2*)p0 = make_float2(v0, v1);
            *(float2*)(p0 + 8 * SS) = make_float2(v2, v3);
        }
    }
}

// ===== prefix softmax =====
__global__ __launch_bounds__(256) void softmax_kernel() {
    int row = blockIdx.x;
    int qr = row & (SS - 1);
    int L = ((qr >> 7) + 1) << 7;
    float* sc = g_sc + (size_t)row * SS;
    int tid = threadIdx.x;
    bool valid = (tid * 4 < L);
    float4 v = valid ? *(float4*)&sc[tid * 4] : make_float4(-1e30f, -1e30f, -1e30f, -1e30f);
    __shared__ float red[8];
    __shared__ float stat;
    float m = fmaxf(fmaxf(v.x, v.y), fmaxf(v.z, v.w));
    for (int o = 16; o; o >>= 1) m = fmaxf(m, __shfl_down_sync(~0u, m, o));
    if ((tid & 31) == 0) red[tid >> 5] = m;
    __syncthreads();
    if (tid == 0) {
        float t = red[0];
        for (int i = 1; i < 8; i++) t = fmaxf(t, red[i]);
        stat = t;
    }
    __syncthreads();
    float mx = stat;
    float e0 = expf(v.x - mx), e1 = expf(v.y - mx), e2 = expf(v.z - mx), e3 = expf(v.w - mx);
    float s = e0 + e1 + e2 + e3;
    for (int o = 16; o; o >>= 1) s += __shfl_down_sync(~0u, s, o);
    __syncthreads();
    if ((tid & 31) == 0) red[tid >> 5] = s;
    __syncthreads();
    if (tid == 0) {
        float t = 0.f;
        for (int i = 0; i < 8; i++) t += red[i];
        stat = t;
    }
    __syncthreads();
    float inv = 1.0f / stat;
    if (valid) *(float4*)&sc[tid * 4] = make_float4(e0 * inv, e1 * inv, e2 * inv, e3 * inv);
}

// ===== tensor-core AV =====
#define AVSM ((2*128 + 2*64)*ASTR*4)

__global__ __launch_bounds__(256)
void attn_av_mma_kernel() {
    int qt = blockIdx.x, bh = blockIdx.y;
    int b = bh >> 4, hh = bh & 15;

    extern __shared__ float sm[];
    float* PH = sm;
    float* PL = PH + 128 * ASTR;
    float* VH = PL + 128 * ASTR;
    float* VL = VH + 64 * ASTR;

    int tid = threadIdx.x, wid = tid >> 5, lane = tid & 31;
    int grp = lane >> 2, qid = lane & 3;
    int wm0 = (wid & 3) * 32, wn0 = (wid >> 2) * 32;

    float acc[2][4][4];
#pragma unroll
    for (int mt = 0; mt < 2; mt++)
#pragma unroll
        for (int nt = 0; nt < 4; nt++)
#pragma unroll
            for (int e = 0; e < 4; e++) acc[mt][nt][e] = 0.f;

    int nchunks = (qt + 1) * 2;
    for (int kc = 0; kc < nchunks; kc++) {
        const float* pb = g_sc + ((size_t)bh * SS + qt * 128) * SS + kc * 64;
        for (int i = tid; i < 128 * 16; i += 256) {
            int row = i >> 4, c4 = (i & 15) * 4;
            float4 v = *(const float4*)(pb + (size_t)row * SS + c4);
            float4 h = hi4(v);
            *(float4*)(PH + row * ASTR + c4) = h;
            *(float4*)(PL + row * ASTR + c4) = lo4(v, h);
        }
        const float* vb = g_qkv + ((size_t)(b * SS + kc * 64)) * QKVS + 2048 + hh * HD;
        for (int i = tid; i < 64 * 16; i += 256) {
            int tok = i >> 4, d4 = (i & 15) * 4;
            float4 v = *(const float4*)(vb + (size_t)tok * QKVS + d4);
            float4 h = hi4(v);
            float4 l = lo4(v, h);
            VH[(d4 + 0) * ASTR + tok] = h.x; VL[(d4 + 0) * ASTR + tok] = l.x;
            VH[(d4 + 1) * ASTR + tok] = h.y; VL[(d4 + 1) * ASTR + tok] = l.y;
            VH[(d4 + 2) * ASTR + tok] = h.z; VL[(d4 + 2) * ASTR + tok] = l.z;
            VH[(d4 + 3) * ASTR + tok] = h.w; VL[(d4 + 3) * ASTR + tok] = l.w;
        }
        __syncthreads();
#pragma unroll
        for (int s = 0; s < 8; s++) {
            int k8 = s * 8;
            unsigned Ah[2][4], Al[2][4];
#pragma unroll
            for (int mt = 0; mt < 2; mt++) {
                int ra = wm0 + mt * 16 + grp;
                Ah[mt][0] = __float_as_uint(PH[ra * ASTR + k8 + qid]);
                Ah[mt][1] = __float_as_uint(PH[(ra + 8) * ASTR + k8 + qid]);
                Ah[mt][2] = __float_as_uint(PH[ra * ASTR + k8 + qid + 4]);
                Ah[mt][3] = __float_as_uint(PH[(ra + 8) * ASTR + k8 + qid + 4]);
                Al[mt][0] = __float_as_uint(PL[ra * ASTR + k8 + qid]);
                Al[mt][1] = __float_as_uint(PL[(ra + 8) * ASTR + k8 + qid]);
                Al[mt][2] = __float_as_uint(PL[ra * ASTR + k8 + qid + 4]);
                Al[mt][3] = __float_as_uint(PL[(ra + 8) * ASTR + k8 + qid + 4]);
            }
#pragma unroll
            for (int nt = 0; nt < 4; nt++) {
                int nr = wn0 + nt * 8 + grp;
                unsigned bh2[2], bl2[2];
                bh2[0] = __float_as_uint(VH[nr * ASTR + k8 + qid]);
                bh2[1] = __float_as_uint(VH[nr * ASTR + k8 + qid + 4]);
                bl2[0] = __float_as_uint(VL[nr * ASTR + k8 + qid]);
                bl2[1] = __float_as_uint(VL[nr * ASTR + k8 + qid + 4]);
#pragma unroll
                for (int mt = 0; mt < 2; mt++) {
                    mma8(acc[mt][nt], Ah[mt], bh2);
                    mma8(acc[mt][nt], Ah[mt], bl2);
                    mma8(acc[mt][nt], Al[mt], bh2);
                }
            }
        }
        __syncthreads();
    }

#pragma unroll
    for (int mt = 0; mt < 2; mt++) {
#pragma unroll
        for (int nt = 0; nt < 4; nt++) {
            int r0 = qt * 128 + wm0 + mt * 16 + grp;
            int c0 = hh * HD + wn0 + nt * 8 + 2 * qid;
            float* p0 = g_a + ((size_t)(b * SS) + r0) * DD + c0;
            *(float2*)p0 = make_float2(acc[mt][nt][0], acc[mt][nt][1]);
            *(float2*)(p0 + 8 * DD) = make_float2(acc[mt][nt][2], acc[mt][nt][3]);
        }
    }
}

// ===== SIMT SGEMM (router GEMM1) =====
__global__ __launch_bounds__(256) void sgemm_kernel(const float* __restrict__ A,
                                                    const float* __restrict__ B,
                                                    const float* __restrict__ bias,
                                                    float* __restrict__ C,
                                                    int M, int N, int K) {
    __shared__ float Ast[16][128];
    __shared__ float Bs[16][64];
    int tid = threadIdx.x;
    int bm = blockIdx.y * 128, bn = blockIdx.x * 64;
    int tx = tid & 15, ty = tid >> 4;
    int m0 = ty * 8, n0 = tx * 4;
    float acc[8][4];
#pragma unroll
    for (int i = 0; i < 8; i++)
#pragma unroll
        for (int j = 0; j < 4; j++) acc[i][j] = 0.f;
    int arow = tid >> 2, ak4 = (tid & 3) * 4, bk = tid >> 4, bc4 = (tid & 15) * 4;
    for (int kb = 0; kb < K; kb += 16) {
#pragma unroll
        for (int p = 0; p < 2; p++) {
            int r = arow + p * 64;
            float4 av = *(const float4*)(A + (size_t)(bm + r) * K + kb + ak4);
            Ast[ak4+0][r] = av.x; Ast[ak4+1][r] = av.y; Ast[ak4+2][r] = av.z; Ast[ak4+3][r] = av.w;
        }
        *(float4*)&Bs[bk][bc4] = *(const float4*)(B + (size_t)(kb + bk) * N + bn + bc4);
        __syncthreads();
#pragma unroll
        for (int k = 0; k < 16; k++) {
            float4 a0 = *(float4*)&Ast[k][m0];
            float4 a1 = *(float4*)&Ast[k][m0 + 4];
            float4 bv = *(float4*)&Bs[k][n0];
            float am[8] = {a0.x,a0.y,a0.z,a0.w,a1.x,a1.y,a1.z,a1.w};
            float bb[4] = {bv.x,bv.y,bv.z,bv.w};
#pragma unroll
            for (int i = 0; i < 8; i++)
#pragma unroll
                for (int j = 0; j < 4; j++) acc[i][j] += am[i] * bb[j];
        }
        __syncthreads();
    }
#pragma unroll
    for (int i = 0; i < 8; i++)
#pragma unroll
        for (int j = 0; j < 4; j++) {
            float v = acc[i][j] + bias[bn + n0 + j];
            C[(size_t)(bm + m0 + i) * N + bn + n0 + j] = fmaxf(v, 0.f);
        }
}

// ===== fused LN: out = LN(in0 + in1 + res + bias); skipMode: keep out row if skip =====
__global__ __launch_bounds__(256) void ln_fused_kernel(const float* __restrict__ in0,
                                                       const float* __restrict__ in1,
                                                       const float* __restrict__ res,
                                                       const float* __restrict__ bias,
                                                       const float* __restrict__ g,
                                                       const float* __restrict__ bsh,
                                                       float* __restrict__ out,
                                                       int skipMode) {
    int row = blockIdx.x;
    if (skipMode && g_skip[row]) return;
    size_t off = (size_t)row * DD;
    int tid = threadIdx.x;
    float4 v = *(const float4*)&in0[off + tid * 4];
    float4 w = *(const float4*)&in1[off + tid * 4];
    float4 r = *(const float4*)&res[off + tid * 4];
    float4 bv = *(const float4*)&bias[tid * 4];
    v.x += w.x + r.x + bv.x; v.y += w.y + r.y + bv.y;
    v.z += w.z + r.z + bv.z; v.w += w.w + r.w + bv.w;
    __shared__ float red[8];
    __shared__ float stat;
    float s = v.x + v.y + v.z + v.w;
    for (int o = 16; o; o >>= 1) s += __shfl_down_sync(~0u, s, o);
    if ((tid & 31) == 0) red[tid >> 5] = s;
    __syncthreads();
    if (tid == 0) {
        float t = 0.f;
        for (int i = 0; i < 8; i++) t += red[i];
        stat = t * (1.0f / DD);
    }
    __syncthreads();
    float mu = stat;
    float dx = v.x - mu, dy = v.y - mu, dz = v.z - mu, dw = v.w - mu;
    float ss = dx * dx + dy * dy + dz * dz + dw * dw;
    for (int o = 16; o; o >>= 1) ss += __shfl_down_sync(~0u, ss, o);
    __syncthreads();
    if ((tid & 31) == 0) red[tid >> 5] = ss;
    __syncthreads();
    if (tid == 0) {
        float t = 0.f;
        for (int i = 0; i < 8; i++) t += red[i];
        stat = rsqrtf(t * (1.0f / DD) + 1e-5f);
    }
    __syncthreads();
    float rs = stat;
    float4 gg = *(const float4*)&g[tid * 4];
    float4 bb = *(const float4*)&bsh[tid * 4];
    *(float4*)&out[off + tid * 4] =
        make_float4(dx * rs * gg.x + bb.x, dy * rs * gg.y + bb.y,
                    dz * rs * gg.z + bb.z, dw * rs * gg.w + bb.w);
}

__global__ __launch_bounds__(256) void router2_kernel(const float* __restrict__ rw2,
                                                      const float* __restrict__ rb2) {
    int w = (blockIdx.x * blockDim.x + threadIdx.x) >> 5;
    int lane = threadIdx.x & 31;
    if (w >= MM) return;
    const float* z = g_zr + (size_t)w * RH;
    float s0 = 0.f, s1 = 0.f, s2 = 0.f;
#pragma unroll
    for (int u = 0; u < 4; u++) {
        int j = lane + 32 * u;
        float zv = z[j];
        s0 += zv * rw2[j * 3 + 0];
        s1 += zv * rw2[j * 3 + 1];
        s2 += zv * rw2[j * 3 + 2];
    }
    for (int o = 16; o; o >>= 1) {
        s0 += __shfl_down_sync(~0u, s0, o);
        s1 += __shfl_down_sync(~0u, s1, o);
        s2 += __shfl_down_sync(~0u, s2, o);
    }
    if (lane == 0) {
        s0 += rb2[0]; s1 += rb2[1]; s2 += rb2[2];
        int a = 0; float best = s0;
        if (s1 > best) { best = s1; a = 1; }
        if (s2 > best) { best = s2; a = 2; }
        g_skip[w] = (a == 0);
        atomicAdd(&g_cnt[a], 1);
    }
}

__global__ void scalars_kernel(float* out) {
    float fs = (float)g_cnt[0], ff = (float)g_cnt[1], fr = (float)g_cnt[2];
    out[(size_t)MM * VOC + 0] = (ff + fr) / (float)MM;
    out[(size_t)MM * VOC + 1] = fs / (float)(MM * NL);
    out[(size_t)MM * VOC + 2] = ff / (float)(MM * NL);
    out[(size_t)MM * VOC + 3] = fr / (float)(MM * NL);
}

extern "C" void kernel_launch(void* const* d_in, const int* in_sizes, int n_in,
                              void* d_out, int out_size) {
    const int*   x    = (const int*)d_in[0];
    const float* emb  = (const float*)d_in[1];
    const float* Wq   = (const float*)d_in[2];
    const float* bq   = (const float*)d_in[3];
    const float* Wk   = (const float*)d_in[4];
    const float* bk   = (const float*)d_in[5];
    const float* Wv   = (const float*)d_in[6];
    const float* bv   = (const float*)d_in[7];
    const float* Wo   = (const float*)d_in[8];
    const float* bo   = (const float*)d_in[9];
    const float* ln1g = (const float*)d_in[10];
    const float* ln1b = (const float*)d_in[11];
    const float* Wf1  = (const float*)d_in[12];
    const float* bf1  = (const float*)d_in[13];
    const float* Wf2  = (const float*)d_in[14];
    const float* bf2  = (const float*)d_in[15];
    const float* ln2g = (const float*)d_in[16];
    const float* ln2b = (const float*)d_in[17];
    const float* rW1  = (const float*)d_in[18];
    const float* rb1  = (const float*)d_in[19];
    const float* rW2  = (const float*)d_in[20];
    const float* rb2  = (const float*)d_in[21];
    const float* Wout = (const float*)d_in[22];
    const float* bout = (const float*)d_in[23];
    float* out = (float*)d_out;

    cudaFuncSetAttribute(tgemm_kernel, cudaFuncAttributeMaxDynamicSharedMemorySize, TGSM);
    cudaFuncSetAttribute(attn_scores_mma_kernel, cudaFuncAttributeMaxDynamicSharedMemorySize, SCSM);
    cudaFuncSetAttribute(attn_av_mma_kernel, cudaFuncAttributeMaxDynamicSharedMemorySize, AVSM);

    float *h, *h1, *t, *t2, *qkv, *a, *f1, *zr;
    float *wqh, *wql, *woh, *wol, *w1h, *w1l, *w2h, *w2l, *wvh, *wvl, *bqkv;
    cudaGetSymbolAddress((void**)&h, g_h);
    cudaGetSymbolAddress((void**)&h1, g_h1);
    cudaGetSymbolAddress((void**)&t, g_t);
    cudaGetSymbolAddress((void**)&t2, g_t2);
    cudaGetSymbolAddress((void**)&qkv, g_qkv);
    cudaGetSymbolAddress((void**)&a, g_a);
    cudaGetSymbolAddress((void**)&f1, g_f1);
    cudaGetSymbolAddress((void**)&zr, g_zr);
    cudaGetSymbolAddress((void**)&wqh, g_wqkv_h);
    cudaGetSymbolAddress((void**)&wql, g_wqkv_l);
    cudaGetSymbolAddress((void**)&woh, g_wo_h);
    cudaGetSymbolAddress((void**)&wol, g_wo_l);
    cudaGetSymbolAddress((void**)&w1h, g_wf1_h);
    cudaGetSymbolAddress((void**)&w1l, g_wf1_l);
    cudaGetSymbolAddress((void**)&w2h, g_wf2_h);
    cudaGetSymbolAddress((void**)&w2l, g_wf2_l);
    cudaGetSymbolAddress((void**)&wvh, g_wout_h);
    cudaGetSymbolAddress((void**)&wvl, g_wout_l);
    cudaGetSymbolAddress((void**)&bqkv, g_bqkv);

    wtrans_kernel<<<dim3(DD/32, DD/32), 256>>>(Wq, wqh, wql, DD, DD);
    wtrans_kernel<<<dim3(DD/32, DD/32), 256>>>(Wk, wqh + (size_t)1024*DD, wql + (size_t)1024*DD, DD, DD);
    wtrans_kernel<<<dim3(DD/32, DD/32), 256>>>(Wv, wqh + (size_t)2048*DD, wql + (size_t)2048*DD, DD, DD);
    wtrans_kernel<<<dim3(DD/32, DD/32), 256>>>(Wo, woh, wol, DD, DD);
    wtrans_kernel<<<dim3(DFF/32, DD/32), 256>>>(Wf1, w1h, w1l, DD, DFF);
    wtrans_kernel<<<dim3(DD/32, DFF/32), 256>>>(Wf2, w2h, w2l, DFF, DD);
    wtrans_kernel<<<dim3(VOC/32, DD/32), 256>>>(Wout, wvh, wvl, DD, VOC);
    bcat_kernel<<<QKVS/256, 256>>>(bq, bk, bv);

    zero_cnt_kernel<<<1, 32>>>();
    embed_kernel<<<MM, 256>>>(x, emb);

    for (int l = 0; l < NL; l++) {
        sgemm_kernel<<<dim3(RH/64, MM/128), 256>>>(h, rW1 + (size_t)l*DD*RH, rb1 + l*RH, zr, MM, RH, DD);
        router2_kernel<<<MM/8, 256>>>(rW2 + (size_t)l*RH*3, rb2 + l*3);
        // QKV
        tgemm_kernel<<<dim3(QKVS/128, MM/128, 1), 256, TGSM>>>(
            h, wqh, wql, bqkv, qkv, nullptr, MM, QKVS, DD, DD, 0);
        attn_scores_mma_kernel<<<dim3(36, BHT), 256, SCSM>>>();
        softmax_kernel<<<BHT*SS, 256>>>();
        attn_av_mma_kernel<<<dim3(SS/128, BHT), 256, AVSM>>>();
        // O-proj split-K x2 -> t, t2 ; LN1(t + t2 + h + bo)
        tgemm_kernel<<<dim3(DD/128, MM/128, 2), 256, TGSM>>>(
            a, woh, wol, nullptr, t, t2, MM, DD, DD/2, DD, 0);
        ln_fused_kernel<<<MM, 256>>>(t, t2, h, bo, ln1g, ln1b, h1, 0);
        // FF1
        tgemm_kernel<<<dim3(DFF/128, MM/128, 1), 256, TGSM>>>(
            h1, w1h, w1l, bf1, f1, nullptr, MM, DFF, DD, DD, 1);
        // FF2 split-K x2 -> t, t2 ; LN2(t + t2 + h1 + bf2), skip-aware write to h
        tgemm_kernel<<<dim3(DD/128, MM/128, 2), 256, TGSM>>>(
            f1, w2h, w2l, nullptr, t, t2, MM, DD, DFF/2, DFF, 0);
        ln_fused_kernel<<<MM, 256>>>(t, t2, h1, bf2, ln2g, ln2b, h, 1);
    }

    tgemm_kernel<<<dim3(VOC/128, MM/128, 1), 256, TGSM>>>(
        h, wvh, wvl, bout, out, nullptr, MM, VOC, DD, DD, 0);
    scalars_kernel<<<1, 1>>>(out);
}

// round 8
// speedup vs baseline: 4.0375x; 1.1001x over previous
#include <cuda_runtime.h>
#include <math.h>
#include <stdint.h>

#define BB 2
#define SS 1024
#define DD 1024
#define NH 16
#define HD 64
#define NL 12
#define DFF 4096
#define RH 128
#define VOC 32000
#define MM (BB*SS)
#define BHT (BB*NH)
#define QKVS 3072

// ---- static scratch ----
__device__ float g_h [MM*DD];
__device__ float g_h1[MM*DD];
__device__ float g_t [MM*DD];
__device__ float g_t2[MM*DD];
__device__ float g_qkv[MM*QKVS];
__device__ float g_a [MM*DD];
__device__ float g_f1[MM*DFF];
__device__ float g_zr[MM*RH];
__device__ float g_sc[(size_t)BHT*SS*SS];
__device__ unsigned char g_skip[MM];
__device__ int g_idx[MM];
__device__ int g_nact;
__device__ int g_cnt[3];
__device__ float g_wqkv_h[(size_t)QKVS*DD], g_wqkv_l[(size_t)QKVS*DD];
__device__ float g_wo_h[(size_t)DD*DD],     g_wo_l[(size_t)DD*DD];
__device__ float g_wf1_h[(size_t)DFF*DD],   g_wf1_l[(size_t)DFF*DD];
__device__ float g_wf2_h[(size_t)DD*DFF],   g_wf2_l[(size_t)DD*DFF];
__device__ float g_wout_h[(size_t)VOC*DD],  g_wout_l[(size_t)VOC*DD];
__device__ float g_bqkv[QKVS];

static __device__ __forceinline__ unsigned smem_u32(const void* p) {
    unsigned r;
    asm("{ .reg .u64 t; cvta.to.shared.u64 t, %1; cvt.u32.u64 %0, t; }" : "=r"(r) : "l"(p));
    return r;
}
static __device__ __forceinline__ float to_tf32f(float x) {
    float r; asm("cvt.rna.tf32.f32 %0, %1;" : "=f"(r) : "f"(x)); return r;
}
static __device__ __forceinline__ void mma8(float* c, const unsigned* a, const unsigned* b) {
    asm volatile(
        "mma.sync.aligned.m16n8k8.row.col.f32.tf32.tf32.f32 "
        "{%0,%1,%2,%3}, {%4,%5,%6,%7}, {%8,%9}, {%0,%1,%2,%3};"
        : "+f"(c[0]), "+f"(c[1]), "+f"(c[2]), "+f"(c[3])
        : "r"(a[0]), "r"(a[1]), "r"(a[2]), "r"(a[3]), "r"(b[0]), "r"(b[1]));
}
static __device__ __forceinline__ float4 hi4(float4 v) {
    return make_float4(to_tf32f(v.x), to_tf32f(v.y), to_tf32f(v.z), to_tf32f(v.w));
}
static __device__ __forceinline__ float4 lo4(float4 v, float4 h) {
    return make_float4(to_tf32f(v.x - h.x), to_tf32f(v.y - h.y),
                       to_tf32f(v.z - h.z), to_tf32f(v.w - h.w));
}
#define CP16(dst, src) \
    asm volatile("cp.async.cg.shared.global [%0], [%1], 16;" :: "r"(dst), "l"(src))

__global__ void zero_cnt_kernel() { if (threadIdx.x < 3) g_cnt[threadIdx.x] = 0; }

// deterministic compaction of active (non-skip) token indices
__global__ __launch_bounds__(1024) void compact_kernel() {
    __shared__ int ps[1024];
    int tid = threadIdx.x;
    int a0 = g_skip[2 * tid] ? 0 : 1;
    int a1 = g_skip[2 * tid + 1] ? 0 : 1;
    ps[tid] = a0 + a1;
    __syncthreads();
    for (int off = 1; off < 1024; off <<= 1) {
        int v = ps[tid];
        int add = (tid >= off) ? ps[tid - off] : 0;
        __syncthreads();
        ps[tid] = v + add;
        __syncthreads();
    }
    int base = ps[tid] - (a0 + a1);
    if (a0) g_idx[base] = 2 * tid;
    if (a1) g_idx[base + a0] = 2 * tid + 1;
    if (tid == 1023) g_nact = ps[1023];
}

// W[K][N] -> Th/Tl [N][K] with tf32 hi/lo split
__global__ __launch_bounds__(256) void wtrans_kernel(const float* __restrict__ W,
                                                     float* __restrict__ Th,
                                                     float* __restrict__ Tl, int K, int N) {
    __shared__ float tile[32][33];
    int n0 = blockIdx.x * 32, k0 = blockIdx.y * 32;
    int tx = threadIdx.x & 31, ty = threadIdx.x >> 5;
    for (int i = ty; i < 32; i += 8) tile[i][tx] = W[(size_t)(k0 + i) * N + n0 + tx];
    __syncthreads();
    for (int i = ty; i < 32; i += 8) {
        float v = tile[tx][i];
        float hv = to_tf32f(v);
        float lv = to_tf32f(v - hv);
        size_t o = (size_t)(n0 + i) * K + k0 + tx;
        Th[o] = hv; Tl[o] = lv;
    }
}

__global__ void bcat_kernel(const float* __restrict__ bq, const float* __restrict__ bk,
                            const float* __restrict__ bv) {
    int i = blockIdx.x * 256 + threadIdx.x;
    g_bqkv[i] = (i < 1024) ? bq[i] : (i < 2048) ? bk[i - 1024] : bv[i - 2048];
}

__global__ __launch_bounds__(256) void embed_kernel(const int* __restrict__ x,
                                                    const float* __restrict__ emb) {
    int tok = blockIdx.x, s = tok % SS, id = x[tok];
    int d0 = threadIdx.x * 4;
    float4 ev = *(const float4*)(emb + (size_t)id * DD + d0);
    float o[4] = {ev.x, ev.y, ev.z, ev.w};
#pragma unroll
    for (int j = 0; j < 4; j++) {
        int d = d0 + j;
        float ang = (float)s * expf((float)(d & ~1) * (-9.210340371976184f / 1024.0f));
        o[j] = o[j] * 32.0f + ((d & 1) ? cosf(ang) : sinf(ang));
    }
    *(float4*)(g_h + (size_t)tok * DD + d0) = make_float4(o[0], o[1], o[2], o[3]);
}

// ===== mma.sync 3xTF32 GEMM, optional split-K (gridDim.z) and row compaction =====
// mode 0: dense rows. mode 1: gather A rows via g_idx (compact output rows).
// mode 2: compact rows (A already compact). Modes 1/2 early-exit past g_nact and guard stores.
#define KCH 16
#define ROWW 20
#define MATB (128*ROWW*4)
#define STGB (3*MATB)
#define TGSM (3*STGB)

__global__ __launch_bounds__(256, 2)
void tgemm_kernel(const float* __restrict__ A, const float* __restrict__ Bh,
                  const float* __restrict__ Bl, const float* __restrict__ bias,
                  float* __restrict__ C0, float* __restrict__ C1,
                  int M, int N, int Ksub, int ldk, int relu, int mode) {
    extern __shared__ char smem[];
    unsigned sb = smem_u32(smem);
    int bm = blockIdx.y * 128, bn = blockIdx.x * 128;
    int Meff = M;
    if (mode) {
        Meff = g_nact;
        if (bm >= Meff) return;
    }
    int z = blockIdx.z;
    A  += (size_t)z * Ksub;
    Bh += (size_t)z * Ksub;
    Bl += (size_t)z * Ksub;
    float* C = z ? C1 : C0;
    int tid = threadIdx.x, wid = tid >> 5, lane = tid & 31;
    int grp = lane >> 2, qid = lane & 3;
    int wm0 = (wid & 3) * 32, wn0 = (wid >> 2) * 64;

    float acc[2][8][4];
#pragma unroll
    for (int mt = 0; mt < 2; mt++)
#pragma unroll
        for (int nt = 0; nt < 8; nt++)
#pragma unroll
            for (int e = 0; e < 4; e++) acc[mt][nt][e] = 0.f;

    int nchunks = Ksub / KCH;
    int r0 = tid >> 2, kc0 = (tid & 3) * 16;
    int r1 = (tid + 256) >> 2, kc1 = ((tid + 256) & 3) * 16;

    // per-thread A row pointers (gather-aware)
    const float *Ar0, *Ar1;
    {
        int rr0 = bm + r0, rr1 = bm + r1;
        if (mode == 1) {
            rr0 = g_idx[rr0 < Meff ? rr0 : Meff - 1];
            rr1 = g_idx[rr1 < Meff ? rr1 : Meff - 1];
        }
        Ar0 = A + (size_t)rr0 * ldk;
        Ar1 = A + (size_t)rr1 * ldk;
    }

#pragma unroll
    for (int c = 0; c < 2; c++) {
        int kb = c * KCH;
        unsigned st = sb + (c % 3) * STGB;
        CP16(st + r0 * 80 + kc0, Ar0 + kb + kc0 / 4);
        CP16(st + r1 * 80 + kc1, Ar1 + kb + kc1 / 4);
        CP16(st + MATB + r0 * 80 + kc0, Bh + (size_t)(bn + r0) * ldk + kb + kc0 / 4);
        CP16(st + MATB + r1 * 80 + kc1, Bh + (size_t)(bn + r1) * ldk + kb + kc1 / 4);
        CP16(st + 2 * MATB + r0 * 80 + kc0, Bl + (size_t)(bn + r0) * ldk + kb + kc0 / 4);
        CP16(st + 2 * MATB + r1 * 80 + kc1, Bl + (size_t)(bn + r1) * ldk + kb + kc1 / 4);
        asm volatile("cp.async.commit_group;");
    }

    for (int c = 0; c < nchunks; c++) {
        if (c + 2 < nchunks) asm volatile("cp.async.wait_group 1;");
        else                 asm volatile("cp.async.wait_group 0;");
        __syncthreads();
        const float* As  = (const float*)(smem + (c % 3) * STGB);
        const float* Bhs = As + 128 * ROWW;
        const float* Bls = Bhs + 128 * ROWW;
#pragma unroll
        for (int s8 = 0; s8 < 2; s8++) {
            int k8 = s8 * 8;
            unsigned Ah[2][4], Al[2][4];
#pragma unroll
            for (int mt = 0; mt < 2; mt++) {
                int ra = wm0 + mt * 16 + grp;
                float x0 = As[ra * ROWW + k8 + qid];
                float x1 = As[(ra + 8) * ROWW + k8 + qid];
                float x2 = As[ra * ROWW + k8 + qid + 4];
                float x3 = As[(ra + 8) * ROWW + k8 + qid + 4];
                float h0 = to_tf32f(x0), h1 = to_tf32f(x1), h2 = to_tf32f(x2), h3 = to_tf32f(x3);
                Ah[mt][0] = __float_as_uint(h0); Ah[mt][1] = __float_as_uint(h1);
                Ah[mt][2] = __float_as_uint(h2); Ah[mt][3] = __float_as_uint(h3);
                Al[mt][0] = __float_as_uint(to_tf32f(x0 - h0));
                Al[mt][1] = __float_as_uint(to_tf32f(x1 - h1));
                Al[mt][2] = __float_as_uint(to_tf32f(x2 - h2));
                Al[mt][3] = __float_as_uint(to_tf32f(x3 - h3));
            }
#pragma unroll
            for (int nt = 0; nt < 8; nt++) {
                int nr = wn0 + nt * 8 + grp;
                unsigned bh[2], bl[2];
                bh[0] = __float_as_uint(Bhs[nr * ROWW + k8 + qid]);
                bh[1] = __float_as_uint(Bhs[nr * ROWW + k8 + qid + 4]);
                bl[0] = __float_as_uint(Bls[nr * ROWW + k8 + qid]);
                bl[1] = __float_as_uint(Bls[nr * ROWW + k8 + qid + 4]);
#pragma unroll
                for (int mt = 0; mt < 2; mt++) {
                    mma8(acc[mt][nt], Ah[mt], bh);
                    mma8(acc[mt][nt], Ah[mt], bl);
                    mma8(acc[mt][nt], Al[mt], bh);
                }
            }
        }
        __syncthreads();
        if (c + 2 < nchunks) {
            int kb = (c + 2) * KCH;
            unsigned st = sb + ((c + 2) % 3) * STGB;
            CP16(st + r0 * 80 + kc0, Ar0 + kb + kc0 / 4);
            CP16(st + r1 * 80 + kc1, Ar1 + kb + kc1 / 4);
            CP16(st + MATB + r0 * 80 + kc0, Bh + (size_t)(bn + r0) * ldk + kb + kc0 / 4);
            CP16(st + MATB + r1 * 80 + kc1, Bh + (size_t)(bn + r1) * ldk + kb + kc1 / 4);
            CP16(st + 2 * MATB + r0 * 80 + kc0, Bl + (size_t)(bn + r0) * ldk + kb + kc0 / 4);
            CP16(st + 2 * MATB + r1 * 80 + kc1, Bl + (size_t)(bn + r1) * ldk + kb + kc1 / 4);
            asm volatile("cp.async.commit_group;");
        }
    }

#pragma unroll
    for (int mt = 0; mt < 2; mt++) {
#pragma unroll
        for (int nt = 0; nt < 8; nt++) {
            int row0 = bm + wm0 + mt * 16 + grp;
            int col = bn + wn0 + nt * 8 + 2 * qid;
            float2 v0 = make_float2(acc[mt][nt][0], acc[mt][nt][1]);
            float2 v1 = make_float2(acc[mt][nt][2], acc[mt][nt][3]);
            if (bias) {
                float2 bv = *(const float2*)(bias + col);
                v0.x += bv.x; v0.y += bv.y; v1.x += bv.x; v1.y += bv.y;
            }
            if (relu) {
                v0.x = fmaxf(v0.x, 0.f); v0.y = fmaxf(v0.y, 0.f);
                v1.x = fmaxf(v1.x, 0.f); v1.y = fmaxf(v1.y, 0.f);
            }
            if (row0 < Meff)
                *(float2*)(C + (size_t)row0 * N + col) = v0;
            if (row0 + 8 < Meff)
                *(float2*)(C + (size_t)(row0 + 8) * N + col) = v1;
        }
    }
}

// ===== tensor-core attention scores: S = Q Kt / 8, lower-triangle 128x128 tiles ====
#define ASTR 68
#define SCSM (4*128*ASTR*4)

__global__ __launch_bounds__(256)
void attn_scores_mma_kernel() {
    int t = blockIdx.x;
    int qt = (int)((sqrtf(8.f * t + 1.f) - 1.f) * 0.5f);
    while ((qt + 1) * (qt + 2) / 2 <= t) qt++;
    while (qt * (qt + 1) / 2 > t) qt--;
    int kt = t - qt * (qt + 1) / 2;
    int bh = blockIdx.y;
    int b = bh >> 4, hh = bh & 15;

    extern __shared__ float sm[];
    float* QH = sm;
    float* QL = QH + 128 * ASTR;
    float* KH = QL + 128 * ASTR;
    float* KL = KH + 128 * ASTR;

    int tid = threadIdx.x, wid = tid >> 5, lane = tid & 31;
    int grp = lane >> 2, qid = lane & 3;
    int wm0 = (wid & 3) * 32, wn0 = (wid >> 2) * 64;

    const float* qb = g_qkv + ((size_t)(b * SS + qt * 128)) * QKVS + hh * HD;
    const float* kb = g_qkv + ((size_t)(b * SS + kt * 128)) * QKVS + 1024 + hh * HD;
    for (int i = tid; i < 128 * 16; i += 256) {
        int row = i >> 4, c4 = (i & 15) * 4;
        float4 v = *(const float4*)(qb + (size_t)row * QKVS + c4);
        float4 h = hi4(v);
        *(float4*)(QH + row * ASTR + c4) = h;
        *(float4*)(QL + row * ASTR + c4) = lo4(v, h);
        float4 w = *(const float4*)(kb + (size_t)row * QKVS + c4);
        float4 wh = hi4(w);
        *(float4*)(KH + row * ASTR + c4) = wh;
        *(float4*)(KL + row * ASTR + c4) = lo4(w, wh);
    }
    __syncthreads();

    float acc[2][8][4];
#pragma unroll
    for (int mt = 0; mt < 2; mt++)
#pragma unroll
        for (int nt = 0; nt < 8; nt++)
#pragma unroll
            for (int e = 0; e < 4; e++) acc[mt][nt][e] = 0.f;

#pragma unroll
    for (int s = 0; s < 8; s++) {
        int k8 = s * 8;
        unsigned Ah[2][4], Al[2][4];
#pragma unroll
        for (int mt = 0; mt < 2; mt++) {
            int ra = wm0 + mt * 16 + grp;
            Ah[mt][0] = __float_as_uint(QH[ra * ASTR + k8 + qid]);
            Ah[mt][1] = __float_as_uint(QH[(ra + 8) * ASTR + k8 + qid]);
            Ah[mt][2] = __float_as_uint(QH[ra * ASTR + k8 + qid + 4]);
            Ah[mt][3] = __float_as_uint(QH[(ra + 8) * ASTR + k8 + qid + 4]);
            Al[mt][0] = __float_as_uint(QL[ra * ASTR + k8 + qid]);
            Al[mt][1] = __float_as_uint(QL[(ra + 8) * ASTR + k8 + qid]);
            Al[mt][2] = __float_as_uint(QL[ra * ASTR + k8 + qid + 4]);
            Al[mt][3] = __float_as_uint(QL[(ra + 8) * ASTR + k8 + qid + 4]);
        }
#pragma unroll
        for (int nt = 0; nt < 8; nt++) {
            int nr = wn0 + nt * 8 + grp;
            unsigned bh2[2], bl2[2];
            bh2[0] = __float_as_uint(KH[nr * ASTR + k8 + qid]);
            bh2[1] = __float_as_uint(KH[nr * ASTR + k8 + qid + 4]);
            bl2[0] = __float_as_uint(KL[nr * ASTR + k8 + qid]);
            bl2[1] = __float_as_uint(KL[nr * ASTR + k8 + qid + 4]);
#pragma unroll
            for (int mt = 0; mt < 2; mt++) {
                mma8(acc[mt][nt], Ah[mt], bh2);
                mma8(acc[mt][nt], Ah[mt], bl2);
                mma8(acc[mt][nt], Al[mt], bh2);
            }
        }
    }

    bool diag = (kt == qt);
#pragma unroll
    for (int mt = 0; mt < 2; mt++) {
#pragma unroll
        for (int nt = 0; nt < 8; nt++) {
            int r0 = qt * 128 + wm0 + mt * 16 + grp;
            int c0 = kt * 128 + wn0 + nt * 8 + 2 * qid;
            float v0 = acc[mt][nt][0] * 0.125f, v1 = acc[mt][nt][1] * 0.125f;
            float v2 = acc[mt][nt][2] * 0.125f, v3 = acc[mt][nt][3] * 0.125f;
            if (diag) {
                if (c0 > r0)     v0 = -1e30f;
                if (c0 + 1 > r0) v1 = -1e30f;
                if (c0 > r0 + 8)     v2 = -1e30f;
                if (c0 + 1 > r0 + 8) v3 = -1e30f;
            }
            float* p0 = g_sc + ((size_t)bh * SS + r0) * SS + c0;
            *(float2*)p0 = make_float2(v0, v1);
            *(float2*)(p0 + 8 * SS) = make_float2(v2, v3);
        }
    }
}

// ===== prefix softmax =====
__global__ __launch_bounds__(256) void softmax_kernel() {
    int row = blockIdx.x;
    int qr = row & (SS - 1);
    int L = ((qr >> 7) + 1) << 7;
    float* sc = g_sc + (size_t)row * SS;
    int tid = threadIdx.x;
    bool valid = (tid * 4 < L);
    float4 v = valid ? *(float4*)&sc[tid * 4] : make_float4(-1e30f, -1e30f, -1e30f, -1e30f);
    __shared__ float red[8];
    __shared__ float stat;
    float m = fmaxf(fmaxf(v.x, v.y), fmaxf(v.z, v.w));
    for (int o = 16; o; o >>= 1) m = fmaxf(m, __shfl_down_sync(~0u, m, o));
    if ((tid & 31) == 0) red[tid >> 5] = m;
    __syncthreads();
    if (tid == 0) {
        float t = red[0];
        for (int i = 1; i < 8; i++) t = fmaxf(t, red[i]);
        stat = t;
    }
    __syncthreads();
    float mx = stat;
    float e0 = expf(v.x - mx), e1 = expf(v.y - mx), e2 = expf(v.z - mx), e3 = expf(v.w - mx);
    float s = e0 + e1 + e2 + e3;
    for (int o = 16; o; o >>= 1) s += __shfl_down_sync(~0u, s, o);
    __syncthreads();
    if ((tid & 31) == 0) red[tid >> 5] = s;
    __syncthreads();
    if (tid == 0) {
        float t = 0.f;
        for (int i = 0; i < 8; i++) t += red[i];
        stat = t;
    }
    __syncthreads();
    float inv = 1.0f / stat;
    if (valid) *(float4*)&sc[tid * 4] = make_float4(e0 * inv, e1 * inv, e2 * inv, e3 * inv);
}

// ===== tensor-core AV =====
#define AVSM ((2*128 + 2*64)*ASTR*4)

__global__ __launch_bounds__(256)
void attn_av_mma_kernel() {
    int qt = blockIdx.x, bh = blockIdx.y;
    int b = bh >> 4, hh = bh & 15;

    extern __shared__ float sm[];
    float* PH = sm;
    float* PL = PH + 128 * ASTR;
    float* VH = PL + 128 * ASTR;
    float* VL = VH + 64 * ASTR;

    int tid = threadIdx.x, wid = tid >> 5, lane = tid & 31;
    int grp = lane >> 2, qid = lane & 3;
    int wm0 = (wid & 3) * 32, wn0 = (wid >> 2) * 32;

    float acc[2][4][4];
#pragma unroll
    for (int mt = 0; mt < 2; mt++)
#pragma unroll
        for (int nt = 0; nt < 4; nt++)
#pragma unroll
            for (int e = 0; e < 4; e++) acc[mt][nt][e] = 0.f;

    int nchunks = (qt + 1) * 2;
    for (int kc = 0; kc < nchunks; kc++) {
        const float* pb = g_sc + ((size_t)bh * SS + qt * 128) * SS + kc * 64;
        for (int i = tid; i < 128 * 16; i += 256) {
            int row = i >> 4, c4 = (i & 15) * 4;
            float4 v = *(const float4*)(pb + (size_t)row * SS + c4);
            float4 h = hi4(v);
            *(float4*)(PH + row * ASTR + c4) = h;
            *(float4*)(PL + row * ASTR + c4) = lo4(v, h);
        }
        const float* vb = g_qkv + ((size_t)(b * SS + kc * 64)) * QKVS + 2048 + hh * HD;
        for (int i = tid; i < 64 * 16; i += 256) {
            int tok = i >> 4, d4 = (i & 15) * 4;
            float4 v = *(const float4*)(vb + (size_t)tok * QKVS + d4);
            float4 h = hi4(v);
            float4 l = lo4(v, h);
            VH[(d4 + 0) * ASTR + tok] = h.x; VL[(d4 + 0) * ASTR + tok] = l.x;
            VH[(d4 + 1) * ASTR + tok] = h.y; VL[(d4 + 1) * ASTR + tok] = l.y;
            VH[(d4 + 2) * ASTR + tok] = h.z; VL[(d4 + 2) * ASTR + tok] = l.z;
            VH[(d4 + 3) * ASTR + tok] = h.w; VL[(d4 + 3) * ASTR + tok] = l.w;
        }
        __syncthreads();
#pragma unroll
        for (int s = 0; s < 8; s++) {
            int k8 = s * 8;
            unsigned Ah[2][4], Al[2][4];
#pragma unroll
            for (int mt = 0; mt < 2; mt++) {
                int ra = wm0 + mt * 16 + grp;
                Ah[mt][0] = __float_as_uint(PH[ra * ASTR + k8 + qid]);
                Ah[mt][1] = __float_as_uint(PH[(ra + 8) * ASTR + k8 + qid]);
                Ah[mt][2] = __float_as_uint(PH[ra * ASTR + k8 + qid + 4]);
                Ah[mt][3] = __float_as_uint(PH[(ra + 8) * ASTR + k8 + qid + 4]);
                Al[mt][0] = __float_as_uint(PL[ra * ASTR + k8 + qid]);
                Al[mt][1] = __float_as_uint(PL[(ra + 8) * ASTR + k8 + qid]);
                Al[mt][2] = __float_as_uint(PL[ra * ASTR + k8 + qid + 4]);
                Al[mt][3] = __float_as_uint(PL[(ra + 8) * ASTR + k8 + qid + 4]);
            }
#pragma unroll
            for (int nt = 0; nt < 4; nt++) {
                int nr = wn0 + nt * 8 + grp;
                unsigned bh2[2], bl2[2];
                bh2[0] = __float_as_uint(VH[nr * ASTR + k8 + qid]);
                bh2[1] = __float_as_uint(VH[nr * ASTR + k8 + qid + 4]);
                bl2[0] = __float_as_uint(VL[nr * ASTR + k8 + qid]);
                bl2[1] = __float_as_uint(VL[nr * ASTR + k8 + qid + 4]);
#pragma unroll
                for (int mt = 0; mt < 2; mt++) {
                    mma8(acc[mt][nt], Ah[mt], bh2);
                    mma8(acc[mt][nt], Ah[mt], bl2);
                    mma8(acc[mt][nt], Al[mt], bh2);
                }
            }
        }
        __syncthreads();
    }

#pragma unroll
    for (int mt = 0; mt < 2; mt++) {
#pragma unroll
        for (int nt = 0; nt < 4; nt++) {
            int r0 = qt * 128 + wm0 + mt * 16 + grp;
            int c0 = hh * HD + wn0 + nt * 8 + 2 * qid;
            float* p0 = g_a + ((size_t)(b * SS) + r0) * DD + c0;
            *(float2*)p0 = make_float2(acc[mt][nt][0], acc[mt][nt][1]);
            *(float2*)(p0 + 8 * DD) = make_float2(acc[mt][nt][2], acc[mt][nt][3]);
        }
    }
}

// ===== SIMT SGEMM (router GEMM1) =====
__global__ __launch_bounds__(256) void sgemm_kernel(const float* __restrict__ A,
                                                    const float* __restrict__ B,
                                                    const float* __restrict__ bias,
                                                    float* __restrict__ C,
                                                    int M, int N, int K) {
    __shared__ float Ast[16][128];
    __shared__ float Bs[16][64];
    int tid = threadIdx.x;
    int bm = blockIdx.y * 128, bn = blockIdx.x * 64;
    int tx = tid & 15, ty = tid >> 4;
    int m0 = ty * 8, n0 = tx * 4;
    float acc[8][4];
#pragma unroll
    for (int i = 0; i < 8; i++)
#pragma unroll
        for (int j = 0; j < 4; j++) acc[i][j] = 0.f;
    int arow = tid >> 2, ak4 = (tid & 3) * 4, bk = tid >> 4, bc4 = (tid & 15) * 4;
    for (int kb = 0; kb < K; kb += 16) {
#pragma unroll
        for (int p = 0; p < 2; p++) {
            int r = arow + p * 64;
            float4 av = *(const float4*)(A + (size_t)(bm + r) * K + kb + ak4);
            Ast[ak4+0][r] = av.x; Ast[ak4+1][r] = av.y; Ast[ak4+2][r] = av.z; Ast[ak4+3][r] = av.w;
        }
        *(float4*)&Bs[bk][bc4] = *(const float4*)(B + (size_t)(kb + bk) * N + bn + bc4);
        __syncthreads();
#pragma unroll
        for (int k = 0; k < 16; k++) {
            float4 a0 = *(float4*)&Ast[k][m0];
            float4 a1 = *(float4*)&Ast[k][m0 + 4];
            float4 bv = *(float4*)&Bs[k][n0];
            float am[8] = {a0.x,a0.y,a0.z,a0.w,a1.x,a1.y,a1.z,a1.w};
            float bb[4] = {bv.x,bv.y,bv.z,bv.w};
#pragma unroll
            for (int i = 0; i < 8; i++)
#pragma unroll
                for (int j = 0; j < 4; j++) acc[i][j] += am[i] * bb[j];
        }
        __syncthreads();
    }
#pragma unroll
    for (int i = 0; i < 8; i++)
#pragma unroll
        for (int j = 0; j < 4; j++) {
            float v = acc[i][j] + bias[bn + n0 + j];
            C[(size_t)(bm + m0 + i) * N + bn + n0 + j] = fmaxf(v, 0.f);
        }
}

// ===== fused LN on compact rows: out = LN(in0 + in1 + res + bias)
// resGather: residual read from full h via g_idx; outScatter: output scattered to full h.
__global__ __launch_bounds__(256) void ln_fused_kernel(const float* __restrict__ in0,
                                                       const float* __restrict__ in1,
                                                       const float* __restrict__ res,
                                                       const float* __restrict__ bias,
                                                       const float* __restrict__ g,
                                                       const float* __restrict__ bsh,
                                                       float* __restrict__ out,
                                                       int resGather, int outScatter) {
    int row = blockIdx.x;
    if (row >= g_nact) return;
    int orow = g_idx[row];
    size_t inoff = (size_t)row * DD;
    size_t resoff = (size_t)(resGather ? orow : row) * DD;
    size_t outoff = (size_t)(outScatter ? orow : row) * DD;
    int tid = threadIdx.x;
    float4 v = *(const float4*)&in0[inoff + tid * 4];
    float4 w = *(const float4*)&in1[inoff + tid * 4];
    float4 r = *(const float4*)&res[resoff + tid * 4];
    float4 bv = *(const float4*)&bias[tid * 4];
    v.x += w.x + r.x + bv.x; v.y += w.y + r.y + bv.y;
    v.z += w.z + r.z + bv.z; v.w += w.w + r.w + bv.w;
    __shared__ float red[8];
    __shared__ float stat;
    float s = v.x + v.y + v.z + v.w;
    for (int o = 16; o; o >>= 1) s += __shfl_down_sync(~0u, s, o);
    if ((tid & 31) == 0) red[tid >> 5] = s;
    __syncthreads();
    if (tid == 0) {
        float t = 0.f;
        for (int i = 0; i < 8; i++) t += red[i];
        stat = t * (1.0f / DD);
    }
    __syncthreads();
    float mu = stat;
    float dx = v.x - mu, dy = v.y - mu, dz = v.z - mu, dw = v.w - mu;
    float ss = dx * dx + dy * dy + dz * dz + dw * dw;
    for (int o = 16; o; o >>= 1) ss += __shfl_down_sync(~0u, ss, o);
    __syncthreads();
    if ((tid & 31) == 0) red[tid >> 5] = ss;
    __syncthreads();
    if (tid == 0) {
        float t = 0.f;
        for (int i = 0; i < 8; i++) t += red[i];
        stat = rsqrtf(t * (1.0f / DD) + 1e-5f);
    }
    __syncthreads();
    float rs = stat;
    float4 gg = *(const float4*)&g[tid * 4];
    float4 bb = *(const float4*)&bsh[tid * 4];
    *(float4*)&out[outoff + tid * 4] =
        make_float4(dx * rs * gg.x + bb.x, dy * rs * gg.y + bb.y,
                    dz * rs * gg.z + bb.z, dw * rs * gg.w + bb.w);
}

__global__ __launch_bounds__(256) void router2_kernel(const float* __restrict__ rw2,
                                                      const float* __restrict__ rb2) {
    int w = (blockIdx.x * blockDim.x + threadIdx.x) >> 5;
    int lane = threadIdx.x & 31;
    if (w >= MM) return;
    const float* z = g_zr + (size_t)w * RH;
    float s0 = 0.f, s1 = 0.f, s2 = 0.f;
#pragma unroll
    for (int u = 0; u < 4; u++) {
        int j = lane + 32 * u;
        float zv = z[j];
        s0 += zv * rw2[j * 3 + 0];
        s1 += zv * rw2[j * 3 + 1];
        s2 += zv * rw2[j * 3 + 2];
    }
    for (int o = 16; o; o >>= 1) {
        s0 += __shfl_down_sync(~0u, s0, o);
        s1 += __shfl_down_sync(~0u, s1, o);
        s2 += __shfl_down_sync(~0u, s2, o);
    }
    if (lane == 0) {
        s0 += rb2[0]; s1 += rb2[1]; s2 += rb2[2];
        int a = 0; float best = s0;
        if (s1 > best) { best = s1; a = 1; }
        if (s2 > best) { best = s2; a = 2; }
        g_skip[w] = (a == 0);
        atomicAdd(&g_cnt[a], 1);
    }
}

__global__ void scalars_kernel(float* out) {
    float fs = (float)g_cnt[0], ff = (float)g_cnt[1], fr = (float)g_cnt[2];
    out[(size_t)MM * VOC + 0] = (ff + fr) / (float)MM;
    out[(size_t)MM * VOC + 1] = fs / (float)(MM * NL);
    out[(size_t)MM * VOC + 2] = ff / (float)(MM * NL);
    out[(size_t)MM * VOC + 3] = fr / (float)(MM * NL);
}

extern "C" void kernel_launch(void* const* d_in, const int* in_sizes, int n_in,
                              void* d_out, int out_size) {
    const int*   x    = (const int*)d_in[0];
    const float* emb  = (const float*)d_in[1];
    const float* Wq   = (const float*)d_in[2];
    const float* bq   = (const float*)d_in[3];
    const float* Wk   = (const float*)d_in[4];
    const float* bk   = (const float*)d_in[5];
    const float* Wv   = (const float*)d_in[6];
    const float* bv   = (const float*)d_in[7];
    const float* Wo   = (const float*)d_in[8];
    const float* bo   = (const float*)d_in[9];
    const float* ln1g = (const float*)d_in[10];
    const float* ln1b = (const float*)d_in[11];
    const float* Wf1  = (const float*)d_in[12];
    const float* bf1  = (const float*)d_in[13];
    const float* Wf2  = (const float*)d_in[14];
    const float* bf2  = (const float*)d_in[15];
    const float* ln2g = (const float*)d_in[16];
    const float* ln2b = (const float*)d_in[17];
    const float* rW1  = (const float*)d_in[18];
    const float* rb1  = (const float*)d_in[19];
    const float* rW2  = (const float*)d_in[20];
    const float* rb2  = (const float*)d_in[21];
    const float* Wout = (const float*)d_in[22];
    const float* bout = (const float*)d_in[23];
    float* out = (float*)d_out;

    cudaFuncSetAttribute(tgemm_kernel, cudaFuncAttributeMaxDynamicSharedMemorySize, TGSM);
    cudaFuncSetAttribute(attn_scores_mma_kernel, cudaFuncAttributeMaxDynamicSharedMemorySize, SCSM);
    cudaFuncSetAttribute(attn_av_mma_kernel, cudaFuncAttributeMaxDynamicSharedMemorySize, AVSM);

    float *h, *h1, *t, *t2, *qkv, *a, *f1, *zr;
    float *wqh, *wql, *woh, *wol, *w1h, *w1l, *w2h, *w2l, *wvh, *wvl, *bqkv;
    cudaGetSymbolAddress((void**)&h, g_h);
    cudaGetSymbolAddress((void**)&h1, g_h1);
    cudaGetSymbolAddress((void**)&t, g_t);
    cudaGetSymbolAddress((void**)&t2, g_t2);
    cudaGetSymbolAddress((void**)&qkv, g_qkv);
    cudaGetSymbolAddress((void**)&a, g_a);
    cudaGetSymbolAddress((void**)&f1, g_f1);
    cudaGetSymbolAddress((void**)&zr, g_zr);
    cudaGetSymbolAddress((void**)&wqh, g_wqkv_h);
    cudaGetSymbolAddress((void**)&wql, g_wqkv_l);
    cudaGetSymbolAddress((void**)&woh, g_wo_h);
    cudaGetSymbolAddress((void**)&wol, g_wo_l);
    cudaGetSymbolAddress((void**)&w1h, g_wf1_h);
    cudaGetSymbolAddress((void**)&w1l, g_wf1_l);
    cudaGetSymbolAddress((void**)&w2h, g_wf2_h);
    cudaGetSymbolAddress((void**)&w2l, g_wf2_l);
    cudaGetSymbolAddress((void**)&wvh, g_wout_h);
    cudaGetSymbolAddress((void**)&wvl, g_wout_l);
    cudaGetSymbolAddress((void**)&bqkv, g_bqkv);

    wtrans_kernel<<<dim3(DD/32, DD/32), 256>>>(Wq, wqh, wql, DD, DD);
    wtrans_kernel<<<dim3(DD/32, DD/32), 256>>>(Wk, wqh + (size_t)1024*DD, wql + (size_t)1024*DD, DD, DD);
    wtrans_kernel<<<dim3(DD/32, DD/32), 256>>>(Wv, wqh + (size_t)2048*DD, wql + (size_t)2048*DD, DD, DD);
    wtrans_kernel<<<dim3(DD/32, DD/32), 256>>>(Wo, woh, wol, DD, DD);
    wtrans_kernel<<<dim3(DFF/32, DD/32), 256>>>(Wf1, w1h, w1l, DD, DFF);
    wtrans_kernel<<<dim3(DD/32, DFF/32), 256>>>(Wf2, w2h, w2l, DFF, DD);
    wtrans_kernel<<<dim3(VOC/32, DD/32), 256>>>(Wout, wvh, wvl, DD, VOC);
    bcat_kernel<<<QKVS/256, 256>>>(bq, bk, bv);

    zero_cnt_kernel<<<1, 32>>>();
    embed_kernel<<<MM, 256>>>(x, emb);

    for (int l = 0; l < NL; l++) {
        sgemm_kernel<<<dim3(RH/64, MM/128), 256>>>(h, rW1 + (size_t)l*DD*RH, rb1 + l*RH, zr, MM, RH, DD);
        router2_kernel<<<MM/8, 256>>>(rW2 + (size_t)l*RH*3, rb2 + l*3);
        compact_kernel<<<1, 1024>>>();
        // QKV (dense: K,V needed for all tokens)
        tgemm_kernel<<<dim3(QKVS/128, MM/128, 1), 256, TGSM>>>(
            h, wqh, wql, bqkv, qkv, nullptr, MM, QKVS, DD, DD, 0, 0);
        attn_scores_mma_kernel<<<dim3(36, BHT), 256, SCSM>>>();
        softmax_kernel<<<BHT*SS, 256>>>();
        attn_av_mma_kernel<<<dim3(SS/128, BHT), 256, AVSM>>>();
        // O-proj on active rows only (gather), split-K x2 -> compact t, t2
        tgemm_kernel<<<dim3(DD/128, MM/128, 2), 256, TGSM>>>(
            a, woh, wol, nullptr, t, t2, MM, DD, DD/2, DD, 0, 1);
        ln_fused_kernel<<<MM, 256>>>(t, t2, h, bo, ln1g, ln1b, h1, 1, 0);
        // FF1 on compact rows
        tgemm_kernel<<<dim3(DFF/128, MM/128, 1), 256, TGSM>>>(
            h1, w1h, w1l, bf1, f1, nullptr, MM, DFF, DD, DD, 1, 2);
        // FF2 compact, split-K x2
        tgemm_kernel<<<dim3(DD/128, MM/128, 2), 256, TGSM>>>(
            f1, w2h, w2l, nullptr, t, t2, MM, DD, DFF/2, DFF, 0, 2);
        // LN2 scatters to h; skipped tokens untouched
        ln_fused_kernel<<<MM, 256>>>(t, t2, h1, bf2, ln2g, ln2b, h, 0, 1);
    }

    tgemm_kernel<<<dim3(VOC/128, MM/128, 1), 256, TGSM>>>(
        h, wvh, wvl, bout, out, nullptr, MM, VOC, DD, DD, 0, 0);
    scalars_kernel<<<1, 1>>>(out);
}